// round 1
// baseline (speedup 1.0000x reference)
#include <cuda_runtime.h>
#include <math.h>

// ---------------- problem constants ----------------
#define BATCH  2
#define SEQ    2048
#define DIM    1024
#define HEADS  16
#define HDK    64
#define FFD    4096
#define MROWS  (BATCH * SEQ)          // 4096
#define SD     (SEQ * DIM)            // 2097152 = 2^21

// ---------------- device scratch (static globals; no allocations) ----------------
__device__ float g_q  [(size_t)MROWS * DIM];
__device__ float g_k  [(size_t)MROWS * DIM];
__device__ float g_v  [(size_t)MROWS * DIM];
__device__ float g_t0 [(size_t)MROWS * DIM];   // attn out / ffn out
__device__ float g_x1 [(size_t)MROWS * DIM];
__device__ float g_x2 [(size_t)MROWS * DIM];
__device__ float g_ffn[(size_t)MROWS * FFD];
__device__ float g_scores[(size_t)BATCH * HEADS * SEQ * SEQ];   // 512 MB
__device__ float g_mean[BATCH * DIM];
__device__ float g_ivar[BATCH * DIM];

// =================================================================
// Generic SGEMM:  C[M,N] = A[M,K] @ W[K,N] + bias   (optional ReLU)
// 64x64 tile, BK=16, 256 threads, 4x4 microtile.
// Requires M,N,K multiples of 64/64/16 (true for all our shapes).
// =================================================================
template<bool RELU>
__global__ void __launch_bounds__(256) gemm_nn_kernel(
    const float* __restrict__ A, const float* __restrict__ W,
    const float* __restrict__ bias, float* __restrict__ C,
    int M, int N, int K)
{
    __shared__ float As[16][64];   // [k][m] (transposed)
    __shared__ float Bs[16][64];   // [k][n]
    const int tid = threadIdx.x;
    const int tx = tid & 15, ty = tid >> 4;
    const int m0 = blockIdx.y * 64, n0 = blockIdx.x * 64;
    const int arow = tid >> 2,  acol = (tid & 3) << 2;    // A tile 64x16
    const int brow = tid >> 4,  bcol = (tid & 15) << 2;   // B tile 16x64
    const float* Ag = A + (size_t)(m0 + arow) * K + acol;
    const float* Bg = W + (size_t)brow * N + n0 + bcol;
    float acc[4][4] = {};
    for (int k0 = 0; k0 < K; k0 += 16) {
        float4 av = *(const float4*)(Ag + k0);
        float4 bv = *(const float4*)(Bg + (size_t)k0 * N);
        As[acol + 0][arow] = av.x;
        As[acol + 1][arow] = av.y;
        As[acol + 2][arow] = av.z;
        As[acol + 3][arow] = av.w;
        *(float4*)(&Bs[brow][bcol]) = bv;
        __syncthreads();
        #pragma unroll
        for (int kk = 0; kk < 16; ++kk) {
            float4 a = *(const float4*)(&As[kk][ty << 2]);
            float4 b = *(const float4*)(&Bs[kk][tx << 2]);
            float ar[4] = {a.x, a.y, a.z, a.w};
            float br[4] = {b.x, b.y, b.z, b.w};
            #pragma unroll
            for (int i = 0; i < 4; ++i)
                #pragma unroll
                for (int j = 0; j < 4; ++j)
                    acc[i][j] += ar[i] * br[j];
        }
        __syncthreads();
    }
    #pragma unroll
    for (int i = 0; i < 4; ++i) {
        const int row = m0 + (ty << 2) + i;
        float4 o;
        float* cp = C + (size_t)row * N + n0 + (tx << 2);
        o.x = acc[i][0] + bias[n0 + (tx << 2) + 0];
        o.y = acc[i][1] + bias[n0 + (tx << 2) + 1];
        o.z = acc[i][2] + bias[n0 + (tx << 2) + 2];
        o.w = acc[i][3] + bias[n0 + (tx << 2) + 3];
        if (RELU) {
            o.x = fmaxf(o.x, 0.f); o.y = fmaxf(o.y, 0.f);
            o.z = fmaxf(o.z, 0.f); o.w = fmaxf(o.w, 0.f);
        }
        *(float4*)cp = o;
    }
}

// =================================================================
// Attention scores (NT GEMM):  S[bh, s, t] = 0.125 * q[b,s,h,:] . k[b,t,h,:]
// Full dk=64 staged in smem. Causal: fully-masked tiles skipped.
// =================================================================
__global__ void __launch_bounds__(256) attn_scores_kernel(
    const float* __restrict__ q, const float* __restrict__ kmat,
    float* __restrict__ scores, int causal)
{
    const int bh = blockIdx.z;
    const int b = bh / HEADS, h = bh % HEADS;
    const int m0 = blockIdx.y * 64, n0 = blockIdx.x * 64;
    if (causal && n0 > m0 + 63) return;   // fully masked tile: never read by softmax
    __shared__ float Qs[HDK][64];   // [dk][s]
    __shared__ float Ks[HDK][64];   // [dk][t]
    const int tid = threadIdx.x;
    const int tx = tid & 15, ty = tid >> 4;
    const int row  = tid >> 2;            // 0..63
    const int col0 = (tid & 3) << 4;      // 0,16,32,48
    const float* qb = q    + ((size_t)b * SEQ + m0 + row) * DIM + h * HDK;
    const float* kb = kmat + ((size_t)b * SEQ + n0 + row) * DIM + h * HDK;
    #pragma unroll
    for (int c = 0; c < 4; ++c) {
        const int cc = col0 + c * 4;
        float4 av = *(const float4*)(qb + cc);
        float4 bv = *(const float4*)(kb + cc);
        Qs[cc + 0][row] = av.x; Qs[cc + 1][row] = av.y;
        Qs[cc + 2][row] = av.z; Qs[cc + 3][row] = av.w;
        Ks[cc + 0][row] = bv.x; Ks[cc + 1][row] = bv.y;
        Ks[cc + 2][row] = bv.z; Ks[cc + 3][row] = bv.w;
    }
    __syncthreads();
    float acc[4][4] = {};
    #pragma unroll
    for (int kk = 0; kk < HDK; ++kk) {
        float4 a = *(const float4*)(&Qs[kk][ty << 2]);
        float4 bfr = *(const float4*)(&Ks[kk][tx << 2]);
        float ar[4] = {a.x, a.y, a.z, a.w};
        float br[4] = {bfr.x, bfr.y, bfr.z, bfr.w};
        #pragma unroll
        for (int i = 0; i < 4; ++i)
            #pragma unroll
            for (int j = 0; j < 4; ++j)
                acc[i][j] += ar[i] * br[j];
    }
    #pragma unroll
    for (int i = 0; i < 4; ++i) {
        float* cp = scores + ((size_t)bh * SEQ + m0 + (ty << 2) + i) * SEQ + n0 + (tx << 2);
        float4 o;
        o.x = 0.125f * acc[i][0]; o.y = 0.125f * acc[i][1];
        o.z = 0.125f * acc[i][2]; o.w = 0.125f * acc[i][3];
        *(float4*)cp = o;
    }
}

// =================================================================
// Row softmax over materialized scores (in place).
// Causal rows: valid j <= i; zero-fill up to the 64-aligned tile edge
// (PV reads whole 64-wide tiles).
// =================================================================
__global__ void __launch_bounds__(128) softmax_kernel(float* __restrict__ sc, int causal)
{
    const int rowid = blockIdx.x;                 // bh*SEQ + i
    const int i = rowid & (SEQ - 1);
    float* p = sc + (size_t)rowid * SEQ;
    const int jvalid = causal ? (i + 1) : SEQ;
    const int jend   = causal ? (((i >> 6) + 1) << 6) : SEQ;
    const int t = threadIdx.x;
    float vals[16];
    float mx = -INFINITY;
    int cnt = 0;
    for (int j = t; j < jvalid; j += 128) {
        float x = p[j];
        vals[cnt++] = x;
        mx = fmaxf(mx, x);
    }
    __shared__ float red[128];
    red[t] = mx; __syncthreads();
    #pragma unroll
    for (int s = 64; s > 0; s >>= 1) {
        if (t < s) red[t] = fmaxf(red[t], red[t + s]);
        __syncthreads();
    }
    mx = red[0]; __syncthreads();
    float sum = 0.f;
    for (int c = 0; c < cnt; ++c) { vals[c] = expf(vals[c] - mx); sum += vals[c]; }
    red[t] = sum; __syncthreads();
    #pragma unroll
    for (int s = 64; s > 0; s >>= 1) {
        if (t < s) red[t] += red[t + s];
        __syncthreads();
    }
    const float inv = 1.f / red[0];
    int c = 0;
    for (int j = t; j < jend; j += 128) {
        p[j] = (j < jvalid) ? vals[c++] * inv : 0.f;
    }
}

// =================================================================
// P @ V (NN GEMM):  out[b,s,h,:] += sum_t P[bh,s,t] * v[b,t,h,:]
// N = 64 (one tile column). Causal: K-loop truncated at diagonal tile.
// =================================================================
__global__ void __launch_bounds__(256) attn_pv_kernel(
    const float* __restrict__ p, const float* __restrict__ v,
    float* __restrict__ outm, int causal)
{
    const int bh = blockIdx.z;
    const int b = bh / HEADS, h = bh % HEADS;
    const int m0 = blockIdx.y * 64;
    __shared__ float Ps[16][64];   // [t][s]
    __shared__ float Vs[16][64];   // [t][dk]
    const int tid = threadIdx.x;
    const int tx = tid & 15, ty = tid >> 4;
    const int arow = tid >> 2,  acol = (tid & 3) << 2;
    const int brow = tid >> 4,  bcol = (tid & 15) << 2;
    const float* Pg = p + ((size_t)bh * SEQ + m0 + arow) * SEQ + acol;
    const float* Vg = v + (size_t)b * SEQ * DIM + h * HDK;
    const int kend = causal ? (m0 + 64) : SEQ;
    float acc[4][4] = {};
    for (int k0 = 0; k0 < kend; k0 += 16) {
        float4 av = *(const float4*)(Pg + k0);
        float4 bv = *(const float4*)(Vg + (size_t)(k0 + brow) * DIM + bcol);
        Ps[acol + 0][arow] = av.x;
        Ps[acol + 1][arow] = av.y;
        Ps[acol + 2][arow] = av.z;
        Ps[acol + 3][arow] = av.w;
        *(float4*)(&Vs[brow][bcol]) = bv;
        __syncthreads();
        #pragma unroll
        for (int kk = 0; kk < 16; ++kk) {
            float4 a = *(const float4*)(&Ps[kk][ty << 2]);
            float4 bfr = *(const float4*)(&Vs[kk][tx << 2]);
            float ar[4] = {a.x, a.y, a.z, a.w};
            float br[4] = {bfr.x, bfr.y, bfr.z, bfr.w};
            #pragma unroll
            for (int i = 0; i < 4; ++i)
                #pragma unroll
                for (int j = 0; j < 4; ++j)
                    acc[i][j] += ar[i] * br[j];
        }
        __syncthreads();
    }
    #pragma unroll
    for (int i = 0; i < 4; ++i) {
        float* cp = outm + ((size_t)b * SEQ + m0 + (ty << 2) + i) * DIM + h * HDK + (tx << 2);
        float4 o; o.x = acc[i][0]; o.y = acc[i][1]; o.z = acc[i][2]; o.w = acc[i][3];
        *(float4*)cp = o;
    }
}

// =================================================================
// Seq-norm (quirk): over axis -2 (sequence), divide by UNBIASED VARIANCE.
// Stats: per (b,d) column, double accumulation.
// =================================================================
__global__ void __launch_bounds__(256) norm_stats_kernel(
    const float* __restrict__ x, const float* __restrict__ res,
    float* __restrict__ meanbuf, float* __restrict__ ivarbuf)
{
    const int d = blockIdx.x * 32 + threadIdx.x;
    const int b = blockIdx.y;
    double s1 = 0.0, s2 = 0.0;
    for (int s = threadIdx.y; s < SEQ; s += 8) {
        const size_t idx = ((size_t)b * SEQ + s) * DIM + d;
        const float vv = x[idx] + res[idx];
        s1 += vv;
        s2 += (double)vv * (double)vv;
    }
    __shared__ double sm1[8][32];
    __shared__ double sm2[8][32];
    sm1[threadIdx.y][threadIdx.x] = s1;
    sm2[threadIdx.y][threadIdx.x] = s2;
    __syncthreads();
    if (threadIdx.y == 0) {
        #pragma unroll
        for (int r = 1; r < 8; ++r) { s1 += sm1[r][threadIdx.x]; s2 += sm2[r][threadIdx.x]; }
        const double m   = s1 / (double)SEQ;
        const double var = (s2 - (double)SEQ * m * m) / (double)(SEQ - 1);
        meanbuf[b * DIM + d] = (float)m;
        ivarbuf[b * DIM + d] = (float)(1.0 / var);
    }
}

__global__ void __launch_bounds__(256) norm_apply_kernel(
    const float* __restrict__ x, const float* __restrict__ res,
    const float* __restrict__ meanbuf, const float* __restrict__ ivarbuf,
    float* __restrict__ out)
{
    const size_t idx = (size_t)blockIdx.x * 256 + threadIdx.x;
    const int d = (int)(idx & (DIM - 1));
    const int b = (int)(idx >> 21);               // SD = 2^21
    const int c = b * DIM + d;
    out[idx] = (x[idx] + res[idx] - meanbuf[c]) * ivarbuf[c];
}

// =================================================================
// Host-side launcher
// =================================================================
extern "C" void kernel_launch(void* const* d_in, const int* in_sizes, int n_in,
                              void* d_out, int out_size)
{
    (void)in_sizes; (void)n_in; (void)out_size;
    const float* dec = (const float*)d_in[0];
    const float* enc = (const float*)d_in[1];
    const float* Wq1 = (const float*)d_in[2];
    const float* Wk1 = (const float*)d_in[3];
    const float* Wv1 = (const float*)d_in[4];
    const float* bq1 = (const float*)d_in[5];
    const float* bk1 = (const float*)d_in[6];
    const float* bv1 = (const float*)d_in[7];
    const float* Wq2 = (const float*)d_in[8];
    const float* Wk2 = (const float*)d_in[9];
    const float* Wv2 = (const float*)d_in[10];
    const float* bq2 = (const float*)d_in[11];
    const float* bk2 = (const float*)d_in[12];
    const float* bv2 = (const float*)d_in[13];
    const float* W1  = (const float*)d_in[14];
    const float* b1  = (const float*)d_in[15];
    const float* W2  = (const float*)d_in[16];
    const float* b2  = (const float*)d_in[17];
    float* out = (float*)d_out;

    float *q, *k, *v, *t0, *x1, *x2, *ffn, *sc, *mn, *iv;
    cudaGetSymbolAddress((void**)&q,   g_q);
    cudaGetSymbolAddress((void**)&k,   g_k);
    cudaGetSymbolAddress((void**)&v,   g_v);
    cudaGetSymbolAddress((void**)&t0,  g_t0);
    cudaGetSymbolAddress((void**)&x1,  g_x1);
    cudaGetSymbolAddress((void**)&x2,  g_x2);
    cudaGetSymbolAddress((void**)&ffn, g_ffn);
    cudaGetSymbolAddress((void**)&sc,  g_scores);
    cudaGetSymbolAddress((void**)&mn,  g_mean);
    cudaGetSymbolAddress((void**)&iv,  g_ivar);

    const dim3 gProj(DIM / 64, MROWS / 64);               // (16, 64)
    const dim3 gFf1 (FFD / 64, MROWS / 64);               // (64, 64)
    const dim3 gSc  (SEQ / 64, SEQ / 64, BATCH * HEADS);  // (32, 32, 32)
    const dim3 gPv  (1,        SEQ / 64, BATCH * HEADS);  // (1, 32, 32)
    const dim3 gSt  (DIM / 32, BATCH);                    // (32, 2)
    const dim3 bSt  (32, 8);
    const int  nSoft = BATCH * HEADS * SEQ;               // 65536
    const int  nApply = (int)(((size_t)MROWS * DIM) / 256);

    // ---------- sublayer 1: causal self-attention ----------
    gemm_nn_kernel<false><<<gProj, 256>>>(dec, Wq1, bq1, q, MROWS, DIM, DIM);
    gemm_nn_kernel<false><<<gProj, 256>>>(dec, Wk1, bk1, k, MROWS, DIM, DIM);
    gemm_nn_kernel<false><<<gProj, 256>>>(dec, Wv1, bv1, v, MROWS, DIM, DIM);
    attn_scores_kernel<<<gSc, 256>>>(q, k, sc, 1);
    softmax_kernel<<<nSoft, 128>>>(sc, 1);
    attn_pv_kernel<<<gPv, 256>>>(sc, v, t0, 1);
    norm_stats_kernel<<<gSt, bSt>>>(t0, dec, mn, iv);
    norm_apply_kernel<<<nApply, 256>>>(t0, dec, mn, iv, x1);

    // ---------- sublayer 2: cross-attention (q from x1, k/v from encoder) ----------
    gemm_nn_kernel<false><<<gProj, 256>>>(x1,  Wq2, bq2, q, MROWS, DIM, DIM);
    gemm_nn_kernel<false><<<gProj, 256>>>(enc, Wk2, bk2, k, MROWS, DIM, DIM);
    gemm_nn_kernel<false><<<gProj, 256>>>(enc, Wv2, bv2, v, MROWS, DIM, DIM);
    attn_scores_kernel<<<gSc, 256>>>(q, k, sc, 0);
    softmax_kernel<<<nSoft, 128>>>(sc, 0);
    attn_pv_kernel<<<gPv, 256>>>(sc, v, t0, 0);
    norm_stats_kernel<<<gSt, bSt>>>(t0, x1, mn, iv);
    norm_apply_kernel<<<nApply, 256>>>(t0, x1, mn, iv, x2);

    // ---------- sublayer 3: FFN ----------
    gemm_nn_kernel<true ><<<gFf1,  256>>>(x2,  W1, b1, ffn, MROWS, FFD, DIM);
    gemm_nn_kernel<false><<<gProj, 256>>>(ffn, W2, b2, t0,  MROWS, DIM, FFD);
    norm_stats_kernel<<<gSt, bSt>>>(t0, x2, mn, iv);
    norm_apply_kernel<<<nApply, 256>>>(t0, x2, mn, iv, out);
}

// round 4
// speedup vs baseline: 2.8877x; 2.8877x over previous
#include <cuda_runtime.h>
#include <cstdint>
#include <math.h>

// ---------------- problem constants ----------------
#define BATCH  2
#define SEQ    2048
#define DIM    1024
#define HEADS  16
#define HDK    64
#define FFD    4096
#define MROWS  (BATCH * SEQ)          // 4096
#define BH     (BATCH * HEADS)        // 32

#define AST 36          // smem A row stride (32 + 4 pad) in floats
#define BKST 36         // smem B k-major row stride
#define ASZ (128 * AST) // one A buffer, floats

// ---------------- device scratch ----------------
__device__ float g_q  [(size_t)MROWS * DIM];
__device__ float g_k  [(size_t)MROWS * DIM];
__device__ float g_v  [(size_t)MROWS * DIM];
__device__ float g_t0 [(size_t)MROWS * DIM];
__device__ float g_x1 [(size_t)MROWS * DIM];
__device__ float g_x2 [(size_t)MROWS * DIM];
__device__ float g_ffn[(size_t)MROWS * FFD];
__device__ float g_scores[(size_t)BH * SEQ * SEQ];      // 512 MB
__device__ float g_mean[BATCH * DIM];
__device__ float g_ivar[BATCH * DIM];

// ---------------- PTX helpers (sm_100 base target; no tcgen05) ----------------
__device__ __forceinline__ uint32_t smem_u32(const void* p) {
    uint32_t a;
    asm("{ .reg .u64 t; cvta.to.shared.u64 t, %1; cvt.u32.u64 %0, t; }" : "=r"(a) : "l"(p));
    return a;
}
__device__ __forceinline__ void cp_async16(uint32_t saddr, const float* g) {
    asm volatile("cp.async.cg.shared.global [%0], [%1], 16;" :: "r"(saddr), "l"(g) : "memory");
}
__device__ __forceinline__ void cp_commit() {
    asm volatile("cp.async.commit_group;" ::: "memory");
}
__device__ __forceinline__ void cp_wait1() {
    asm volatile("cp.async.wait_group 1;" ::: "memory");
}
__device__ __forceinline__ uint32_t cvt_tf32(float f) {
    uint32_t r;
    asm("cvt.rna.tf32.f32 %0, %1;" : "=r"(r) : "f"(f));
    return r;
}
__device__ __forceinline__ void mma_tf32(float c[4],
    uint32_t a0, uint32_t a1, uint32_t a2, uint32_t a3, uint32_t b0, uint32_t b1) {
    asm volatile(
        "mma.sync.aligned.m16n8k8.row.col.f32.tf32.tf32.f32 "
        "{%0,%1,%2,%3}, {%4,%5,%6,%7}, {%8,%9}, {%0,%1,%2,%3};"
        : "+f"(c[0]), "+f"(c[1]), "+f"(c[2]), "+f"(c[3])
        : "r"(a0), "r"(a1), "r"(a2), "r"(a3), "r"(b0), "r"(b1));
}

// ---------------- tile loaders (cp.async, 256 threads) ----------------
__device__ __forceinline__ void load_A(uint32_t sbase, const float* A, int lda, int k0) {
    const int t = threadIdx.x;
    #pragma unroll
    for (int j = 0; j < 4; ++j) {                 // 128 x 32 floats
        const int idx = t + (j << 8);
        const int row = idx >> 3, c4 = (idx & 7) << 2;
        cp_async16(sbase + (uint32_t)(row * AST + c4) * 4, A + (size_t)row * lda + k0 + c4);
    }
}
template<int BN>
__device__ __forceinline__ void load_B_k(uint32_t sbase, const float* B, int ldb, int k0) {
    const int t = threadIdx.x;
    #pragma unroll
    for (int j = 0; j < BN / 32; ++j) {           // BN x 32 floats
        const int idx = t + (j << 8);
        const int row = idx >> 3, c4 = (idx & 7) << 2;
        cp_async16(sbase + (uint32_t)(row * BKST + c4) * 4, B + (size_t)row * ldb + k0 + c4);
    }
}
template<int BN>
__device__ __forceinline__ void load_B_n(uint32_t sbase, const float* B, int ldb, int k0) {
    const int t = threadIdx.x;
    const int f4perrow = BN / 4;                  // 32 or 16
    #pragma unroll
    for (int j = 0; j < (32 * BN) / 1024; ++j) {  // 32 x BN floats
        const int idx = t + (j << 8);
        const int row = idx / f4perrow, c4 = (idx % f4perrow) << 2;
        cp_async16(sbase + (uint32_t)(row * (BN + 8) + c4) * 4, B + (size_t)(k0 + row) * ldb + c4);
    }
}

// ---------------- warp mma compute on one BK=32 stage ----------------
template<int BN, bool BKMAJ>
__device__ __forceinline__ void compute_tile(const float* sA, const float* sB,
                                             float acc[2][BN / 16][4]) {
    const int lane = threadIdx.x & 31, warp = threadIdx.x >> 5;
    const int wm = warp >> 1, wn = warp & 1;
    const int g = lane >> 2, tig = lane & 3;
    constexpr int NT = BN / 16;
    #pragma unroll
    for (int s = 0; s < 4; ++s) {
        const int kk = s << 3;
        uint32_t a[2][4];
        #pragma unroll
        for (int mt = 0; mt < 2; ++mt) {
            const float* ap = sA + (wm * 32 + mt * 16 + g) * AST + kk + tig;
            a[mt][0] = cvt_tf32(ap[0]);
            a[mt][1] = cvt_tf32(ap[8 * AST]);
            a[mt][2] = cvt_tf32(ap[4]);
            a[mt][3] = cvt_tf32(ap[8 * AST + 4]);
        }
        #pragma unroll
        for (int nt = 0; nt < NT; ++nt) {
            const int n = wn * (BN / 2) + nt * 8 + g;
            uint32_t b0, b1;
            if (BKMAJ) {
                const float* bp = sB + n * BKST + kk + tig;
                b0 = cvt_tf32(bp[0]);
                b1 = cvt_tf32(bp[4]);
            } else {
                const float* bp = sB + (kk + tig) * (BN + 8) + n;
                b0 = cvt_tf32(bp[0]);
                b1 = cvt_tf32(bp[4 * (BN + 8)]);
            }
            mma_tf32(acc[0][nt], a[0][0], a[0][1], a[0][2], a[0][3], b0, b1);
            mma_tf32(acc[1][nt], a[1][0], a[1][1], a[1][2], a[1][3], b0, b1);
        }
    }
}

// ---------------- double-buffered mainloop ----------------
template<int BN, bool BKMAJ>
__device__ __forceinline__ void mainloop(const float* A, int lda,
                                         const float* B, int ldb, int kiters,
                                         float* sA, float* sB,
                                         float acc[2][BN / 16][4]) {
    constexpr int BSZ = BKMAJ ? BN * BKST : 32 * (BN + 8);
    const uint32_t sa = smem_u32(sA), sb = smem_u32(sB);
    load_A(sa, A, lda, 0);
    if (BKMAJ) load_B_k<BN>(sb, B, ldb, 0); else load_B_n<BN>(sb, B, ldb, 0);
    cp_commit();
    for (int it = 0; it < kiters; ++it) {
        const int cur = it & 1, nxt = cur ^ 1;
        if (it + 1 < kiters) {
            load_A(sa + nxt * ASZ * 4, A, lda, (it + 1) * 32);
            if (BKMAJ) load_B_k<BN>(sb + nxt * BSZ * 4, B, ldb, (it + 1) * 32);
            else       load_B_n<BN>(sb + nxt * BSZ * 4, B, ldb, (it + 1) * 32);
        }
        cp_commit();
        cp_wait1();
        __syncthreads();
        compute_tile<BN, BKMAJ>(sA + cur * ASZ, sB + cur * BSZ, acc);
        __syncthreads();
    }
}

// =================================================================
// Linear: C[M,N] = A[M,K] @ W[K,N] + bias (optional ReLU). B n-major.
// =================================================================
template<bool RELU>
__global__ void __launch_bounds__(256) mma_linear(
    const float* __restrict__ A, const float* __restrict__ W,
    const float* __restrict__ bias, float* __restrict__ C, int K, int N)
{
    extern __shared__ float sm[];
    float* sA = sm;
    float* sB = sm + 2 * ASZ;
    const int m0 = blockIdx.y << 7, n0 = blockIdx.x << 7;
    float acc[2][8][4] = {};
    mainloop<128, false>(A + (size_t)m0 * K, K, W + n0, N, K >> 5, sA, sB, acc);
    const int lane = threadIdx.x & 31, warp = threadIdx.x >> 5;
    const int wm = warp >> 1, wn = warp & 1;
    const int g = lane >> 2, tig = lane & 3;
    #pragma unroll
    for (int mt = 0; mt < 2; ++mt)
        #pragma unroll
        for (int nt = 0; nt < 8; ++nt) {
            const int row = m0 + wm * 32 + mt * 16 + g;
            const int col = n0 + wn * 64 + nt * 8 + tig * 2;
            float2 bv = *(const float2*)(bias + col);
            float2 o0, o1;
            o0.x = acc[mt][nt][0] + bv.x; o0.y = acc[mt][nt][1] + bv.y;
            o1.x = acc[mt][nt][2] + bv.x; o1.y = acc[mt][nt][3] + bv.y;
            if (RELU) {
                o0.x = fmaxf(o0.x, 0.f); o0.y = fmaxf(o0.y, 0.f);
                o1.x = fmaxf(o1.x, 0.f); o1.y = fmaxf(o1.y, 0.f);
            }
            *(float2*)(C + (size_t)row * N + col) = o0;
            *(float2*)(C + (size_t)(row + 8) * N + col) = o1;
        }
}

// =================================================================
// Scores: S[z,s,t] = 0.125 * q.k  (B k-major, K = HDK = 64)
// =================================================================
__global__ void __launch_bounds__(256) mma_scores(
    const float* __restrict__ q, const float* __restrict__ kmat,
    float* __restrict__ sc, int causal)
{
    const int z = blockIdx.z, b = z >> 4, h = z & 15;
    const int m0 = blockIdx.y << 7, n0 = blockIdx.x << 7;
    if (causal && n0 > m0) return;
    extern __shared__ float sm[];
    float* sA = sm;
    float* sB = sm + 2 * ASZ;
    float acc[2][8][4] = {};
    mainloop<128, true>(q + ((size_t)b * SEQ + m0) * DIM + h * HDK, DIM,
                        kmat + ((size_t)b * SEQ + n0) * DIM + h * HDK, DIM,
                        2, sA, sB, acc);
    const int lane = threadIdx.x & 31, warp = threadIdx.x >> 5;
    const int wm = warp >> 1, wn = warp & 1;
    const int g = lane >> 2, tig = lane & 3;
    float* base = sc + (size_t)z * SEQ * SEQ;
    #pragma unroll
    for (int mt = 0; mt < 2; ++mt)
        #pragma unroll
        for (int nt = 0; nt < 8; ++nt) {
            const int row = m0 + wm * 32 + mt * 16 + g;
            const int col = n0 + wn * 64 + nt * 8 + tig * 2;
            float2 o0, o1;
            o0.x = 0.125f * acc[mt][nt][0]; o0.y = 0.125f * acc[mt][nt][1];
            o1.x = 0.125f * acc[mt][nt][2]; o1.y = 0.125f * acc[mt][nt][3];
            *(float2*)(base + (size_t)row * SEQ + col) = o0;
            *(float2*)(base + (size_t)(row + 8) * SEQ + col) = o1;
        }
}

// =================================================================
// PV: out[b,s,h,:] = P[z,s,:] @ V[b,:,h,:]   (B n-major, BN = 64)
// =================================================================
__global__ void __launch_bounds__(256) mma_pv(
    const float* __restrict__ p, const float* __restrict__ v,
    float* __restrict__ outm, int causal)
{
    const int z = blockIdx.z, b = z >> 4, h = z & 15;
    const int m0 = blockIdx.y << 7;
    extern __shared__ float sm[];
    float* sA = sm;
    float* sB = sm + 2 * ASZ;
    const int kiters = (causal ? (m0 + 128) : SEQ) >> 5;
    float acc[2][4][4] = {};
    mainloop<64, false>(p + (size_t)z * SEQ * SEQ + (size_t)m0 * SEQ, SEQ,
                        v + (size_t)b * SEQ * DIM + h * HDK, DIM,
                        kiters, sA, sB, acc);
    const int lane = threadIdx.x & 31, warp = threadIdx.x >> 5;
    const int wm = warp >> 1, wn = warp & 1;
    const int g = lane >> 2, tig = lane & 3;
    #pragma unroll
    for (int mt = 0; mt < 2; ++mt)
        #pragma unroll
        for (int nt = 0; nt < 4; ++nt) {
            const int row = m0 + wm * 32 + mt * 16 + g;
            const int col = wn * 32 + nt * 8 + tig * 2;
            float* cp0 = outm + ((size_t)b * SEQ + row) * DIM + h * HDK + col;
            float2 o0, o1;
            o0.x = acc[mt][nt][0]; o0.y = acc[mt][nt][1];
            o1.x = acc[mt][nt][2]; o1.y = acc[mt][nt][3];
            *(float2*)cp0 = o0;
            *(float2*)(cp0 + 8 * DIM) = o1;
        }
}

// =================================================================
// Softmax (in place; zero-fill to 128-aligned edge for PV tiles)
// =================================================================
__global__ void __launch_bounds__(128) softmax_kernel(float* __restrict__ sc, int causal)
{
    const int rowid = blockIdx.x;
    const int i = rowid & (SEQ - 1);
    float* p = sc + (size_t)rowid * SEQ;
    const int jvalid = causal ? (i + 1) : SEQ;
    const int jend   = causal ? (((i >> 7) + 1) << 7) : SEQ;
    const int t = threadIdx.x;
    float vals[16];
    float mx = -INFINITY;
    int cnt = 0;
    for (int j = t; j < jvalid; j += 128) {
        float x = p[j];
        vals[cnt++] = x;
        mx = fmaxf(mx, x);
    }
    __shared__ float red[128];
    red[t] = mx; __syncthreads();
    #pragma unroll
    for (int s = 64; s > 0; s >>= 1) {
        if (t < s) red[t] = fmaxf(red[t], red[t + s]);
        __syncthreads();
    }
    mx = red[0]; __syncthreads();
    float sum = 0.f;
    for (int c = 0; c < cnt; ++c) { vals[c] = expf(vals[c] - mx); sum += vals[c]; }
    red[t] = sum; __syncthreads();
    #pragma unroll
    for (int s = 64; s > 0; s >>= 1) {
        if (t < s) red[t] += red[t + s];
        __syncthreads();
    }
    const float inv = 1.f / red[0];
    int c = 0;
    for (int j = t; j < jend; j += 128)
        p[j] = (j < jvalid) ? vals[c++] * inv : 0.f;
}

// =================================================================
// Seq-norm (quirk: normalize over S, divide by unbiased VARIANCE)
// =================================================================
__global__ void __launch_bounds__(256) norm_stats_kernel(
    const float* __restrict__ x, const float* __restrict__ res,
    float* __restrict__ meanbuf, float* __restrict__ ivarbuf)
{
    const int d = blockIdx.x * 32 + threadIdx.x;
    const int b = blockIdx.y;
    double s1 = 0.0, s2 = 0.0;
    for (int s = threadIdx.y; s < SEQ; s += 8) {
        const size_t idx = ((size_t)b * SEQ + s) * DIM + d;
        const float vv = x[idx] + res[idx];
        s1 += vv;
        s2 += (double)vv * (double)vv;
    }
    __shared__ double sm1[8][32];
    __shared__ double sm2[8][32];
    sm1[threadIdx.y][threadIdx.x] = s1;
    sm2[threadIdx.y][threadIdx.x] = s2;
    __syncthreads();
    if (threadIdx.y == 0) {
        #pragma unroll
        for (int r = 1; r < 8; ++r) { s1 += sm1[r][threadIdx.x]; s2 += sm2[r][threadIdx.x]; }
        const double m   = s1 / (double)SEQ;
        const double var = (s2 - (double)SEQ * m * m) / (double)(SEQ - 1);
        meanbuf[b * DIM + d] = (float)m;
        ivarbuf[b * DIM + d] = (float)(1.0 / var);
    }
}

__global__ void __launch_bounds__(256) norm_apply_kernel(
    const float* __restrict__ x, const float* __restrict__ res,
    const float* __restrict__ meanbuf, const float* __restrict__ ivarbuf,
    float* __restrict__ out)
{
    const size_t idx = (size_t)blockIdx.x * 256 + threadIdx.x;
    const int d = (int)(idx & (DIM - 1));
    const int b = (int)(idx >> 21);
    const int c = b * DIM + d;
    out[idx] = (x[idx] + res[idx] - meanbuf[c]) * ivarbuf[c];
}

// =================================================================
// Host-side launcher
// =================================================================
extern "C" void kernel_launch(void* const* d_in, const int* in_sizes, int n_in,
                              void* d_out, int out_size)
{
    (void)in_sizes; (void)n_in; (void)out_size;
    const float* dec = (const float*)d_in[0];
    const float* enc = (const float*)d_in[1];
    const float* Wq1 = (const float*)d_in[2];
    const float* Wk1 = (const float*)d_in[3];
    const float* Wv1 = (const float*)d_in[4];
    const float* bq1 = (const float*)d_in[5];
    const float* bk1 = (const float*)d_in[6];
    const float* bv1 = (const float*)d_in[7];
    const float* Wq2 = (const float*)d_in[8];
    const float* Wk2 = (const float*)d_in[9];
    const float* Wv2 = (const float*)d_in[10];
    const float* bq2 = (const float*)d_in[11];
    const float* bk2 = (const float*)d_in[12];
    const float* bv2 = (const float*)d_in[13];
    const float* W1  = (const float*)d_in[14];
    const float* b1  = (const float*)d_in[15];
    const float* W2  = (const float*)d_in[16];
    const float* b2  = (const float*)d_in[17];
    float* out = (float*)d_out;

    float *q, *k, *v, *t0, *x1, *x2, *ffn, *sc, *mn, *iv;
    cudaGetSymbolAddress((void**)&q,   g_q);
    cudaGetSymbolAddress((void**)&k,   g_k);
    cudaGetSymbolAddress((void**)&v,   g_v);
    cudaGetSymbolAddress((void**)&t0,  g_t0);
    cudaGetSymbolAddress((void**)&x1,  g_x1);
    cudaGetSymbolAddress((void**)&x2,  g_x2);
    cudaGetSymbolAddress((void**)&ffn, g_ffn);
    cudaGetSymbolAddress((void**)&sc,  g_scores);
    cudaGetSymbolAddress((void**)&mn,  g_mean);
    cudaGetSymbolAddress((void**)&iv,  g_ivar);

    // dynamic smem sizes (bytes)
    const int SM_LIN = (2 * ASZ + 2 * 32 * (128 + 8)) * 4;   // 71680
    const int SM_SC  = (2 * ASZ + 2 * 128 * BKST) * 4;       // 73728
    const int SM_PV  = (2 * ASZ + 2 * 32 * (64 + 8)) * 4;    // 55296
    cudaFuncSetAttribute(mma_linear<false>, cudaFuncAttributeMaxDynamicSharedMemorySize, SM_LIN);
    cudaFuncSetAttribute(mma_linear<true>,  cudaFuncAttributeMaxDynamicSharedMemorySize, SM_LIN);
    cudaFuncSetAttribute(mma_scores,        cudaFuncAttributeMaxDynamicSharedMemorySize, SM_SC);
    cudaFuncSetAttribute(mma_pv,            cudaFuncAttributeMaxDynamicSharedMemorySize, SM_PV);

    const dim3 gProj(DIM / 128, MROWS / 128);            // (8, 32)
    const dim3 gFf1 (FFD / 128, MROWS / 128);            // (32, 32)
    const dim3 gSc  (SEQ / 128, SEQ / 128, BH);          // (16, 16, 32)
    const dim3 gPv  (1,         SEQ / 128, BH);          // (1, 16, 32)
    const dim3 bT(32, 8);
    const dim3 gSt(DIM / 32, BATCH);
    const int  nSoft  = BH * SEQ;
    const int  nApply = (int)(((size_t)MROWS * DIM) / 256);

    // ---------- sublayer 1: causal self-attention ----------
    mma_linear<false><<<gProj, 256, SM_LIN>>>(dec, Wq1, bq1, q, DIM, DIM);
    mma_linear<false><<<gProj, 256, SM_LIN>>>(dec, Wk1, bk1, k, DIM, DIM);
    mma_linear<false><<<gProj, 256, SM_LIN>>>(dec, Wv1, bv1, v, DIM, DIM);
    mma_scores<<<gSc, 256, SM_SC>>>(q, k, sc, 1);
    softmax_kernel<<<nSoft, 128>>>(sc, 1);
    mma_pv<<<gPv, 256, SM_PV>>>(sc, v, t0, 1);
    norm_stats_kernel<<<gSt, bT>>>(t0, dec, mn, iv);
    norm_apply_kernel<<<nApply, 256>>>(t0, dec, mn, iv, x1);

    // ---------- sublayer 2: cross-attention ----------
    mma_linear<false><<<gProj, 256, SM_LIN>>>(x1,  Wq2, bq2, q, DIM, DIM);
    mma_linear<false><<<gProj, 256, SM_LIN>>>(enc, Wk2, bk2, k, DIM, DIM);
    mma_linear<false><<<gProj, 256, SM_LIN>>>(enc, Wv2, bv2, v, DIM, DIM);
    mma_scores<<<gSc, 256, SM_SC>>>(q, k, sc, 0);
    softmax_kernel<<<nSoft, 128>>>(sc, 0);
    mma_pv<<<gPv, 256, SM_PV>>>(sc, v, t0, 0);
    norm_stats_kernel<<<gSt, bT>>>(t0, x1, mn, iv);
    norm_apply_kernel<<<nApply, 256>>>(t0, x1, mn, iv, x2);

    // ---------- sublayer 3: FFN ----------
    mma_linear<true ><<<gFf1,  256, SM_LIN>>>(x2,  W1, b1, ffn, DIM, FFD);
    mma_linear<false><<<gProj, 256, SM_LIN>>>(ffn, W2, b2, t0, FFD, DIM);
    norm_stats_kernel<<<gSt, bT>>>(t0, x2, mn, iv);
    norm_apply_kernel<<<nApply, 256>>>(t0, x2, mn, iv, out);
}

// round 6
// speedup vs baseline: 4.2025x; 1.4553x over previous
#include <cuda_runtime.h>
#include <cuda_fp16.h>
#include <cstdint>
#include <math.h>

// ---------------- problem constants ----------------
#define BATCH  2
#define SEQ    2048
#define DIM    1024
#define HEADS  16
#define HDK    64
#define FFD    4096
#define MROWS  (BATCH * SEQ)          // 4096
#define BH     (BATCH * HEADS)        // 32

#define AST 36          // smem A row stride (32 + 4 pad) in floats (linear GEMM)
#define ASZ (128 * AST) // one A buffer, floats

// flash smem strides (halves)
#define QST 72
#define KST 72
#define VST 136
#define FA_SMEM ((2 * 128 * QST + HDK * VST) * 2)   // 54272 bytes

// ---------------- device scratch ----------------
__device__ float  g_v  [(size_t)MROWS * DIM];
__device__ float  g_t0 [(size_t)MROWS * DIM];
__device__ float  g_x1 [(size_t)MROWS * DIM];
__device__ float  g_x2 [(size_t)MROWS * DIM];
__device__ float  g_ffn[(size_t)MROWS * FFD];
__device__ float  g_mean[BATCH * DIM];
__device__ float  g_ivar[BATCH * DIM];
__device__ __half g_qh [(size_t)MROWS * DIM];
__device__ __half g_kh [(size_t)MROWS * DIM];
__device__ __half g_vt [(size_t)BH * HDK * SEQ];

// ---------------- PTX helpers (sm_100 base target) ----------------
__device__ __forceinline__ uint32_t smem_u32(const void* p) {
    uint32_t a;
    asm("{ .reg .u64 t; cvta.to.shared.u64 t, %1; cvt.u32.u64 %0, t; }" : "=r"(a) : "l"(p));
    return a;
}
__device__ __forceinline__ void cp_async16(uint32_t saddr, const void* g) {
    asm volatile("cp.async.cg.shared.global [%0], [%1], 16;" :: "r"(saddr), "l"(g) : "memory");
}
__device__ __forceinline__ void cp_commit() {
    asm volatile("cp.async.commit_group;" ::: "memory");
}
__device__ __forceinline__ void cp_wait1() {
    asm volatile("cp.async.wait_group 1;" ::: "memory");
}
__device__ __forceinline__ void cp_wait0() {
    asm volatile("cp.async.wait_group 0;" ::: "memory");
}
__device__ __forceinline__ uint32_t cvt_tf32(float f) {
    uint32_t r;
    asm("cvt.rna.tf32.f32 %0, %1;" : "=r"(r) : "f"(f));
    return r;
}
__device__ __forceinline__ void mma_tf32(float c[4],
    uint32_t a0, uint32_t a1, uint32_t a2, uint32_t a3, uint32_t b0, uint32_t b1) {
    asm volatile(
        "mma.sync.aligned.m16n8k8.row.col.f32.tf32.tf32.f32 "
        "{%0,%1,%2,%3}, {%4,%5,%6,%7}, {%8,%9}, {%0,%1,%2,%3};"
        : "+f"(c[0]), "+f"(c[1]), "+f"(c[2]), "+f"(c[3])
        : "r"(a0), "r"(a1), "r"(a2), "r"(a3), "r"(b0), "r"(b1));
}
__device__ __forceinline__ void mma_f16(float c[4],
    uint32_t a0, uint32_t a1, uint32_t a2, uint32_t a3, uint32_t b0, uint32_t b1) {
    asm volatile(
        "mma.sync.aligned.m16n8k16.row.col.f32.f16.f16.f32 "
        "{%0,%1,%2,%3}, {%4,%5,%6,%7}, {%8,%9}, {%0,%1,%2,%3};"
        : "+f"(c[0]), "+f"(c[1]), "+f"(c[2]), "+f"(c[3])
        : "r"(a0), "r"(a1), "r"(a2), "r"(a3), "r"(b0), "r"(b1));
}
__device__ __forceinline__ uint32_t pack_h2(float x, float y) {
    __half2 h = __floats2half2_rn(x, y);
    return *(uint32_t*)&h;
}

// =================================================================
// Linear GEMM (tf32): C = A[M,K] @ W[K,N] + bias. Optional ReLU / half out.
// =================================================================
__device__ __forceinline__ void load_A(uint32_t sbase, const float* A, int lda, int k0) {
    const int t = threadIdx.x;
    #pragma unroll
    for (int j = 0; j < 4; ++j) {
        const int idx = t + (j << 8);
        const int row = idx >> 3, c4 = (idx & 7) << 2;
        cp_async16(sbase + (uint32_t)(row * AST + c4) * 4, A + (size_t)row * lda + k0 + c4);
    }
}
__device__ __forceinline__ void load_B_n(uint32_t sbase, const float* B, int ldb, int k0) {
    const int t = threadIdx.x;
    #pragma unroll
    for (int j = 0; j < 4; ++j) {                 // 32 x 128 floats
        const int idx = t + (j << 8);
        const int row = idx >> 5, c4 = (idx & 31) << 2;
        cp_async16(sbase + (uint32_t)(row * 136 + c4) * 4, B + (size_t)(k0 + row) * ldb + c4);
    }
}
__device__ __forceinline__ void compute_tile_lin(const float* sA, const float* sB,
                                                 float acc[2][8][4]) {
    const int lane = threadIdx.x & 31, warp = threadIdx.x >> 5;
    const int wm = warp >> 1, wn = warp & 1;
    const int g = lane >> 2, tig = lane & 3;
    #pragma unroll
    for (int s = 0; s < 4; ++s) {
        const int kk = s << 3;
        uint32_t a[2][4];
        #pragma unroll
        for (int mt = 0; mt < 2; ++mt) {
            const float* ap = sA + (wm * 32 + mt * 16 + g) * AST + kk + tig;
            a[mt][0] = cvt_tf32(ap[0]);
            a[mt][1] = cvt_tf32(ap[8 * AST]);
            a[mt][2] = cvt_tf32(ap[4]);
            a[mt][3] = cvt_tf32(ap[8 * AST + 4]);
        }
        #pragma unroll
        for (int nt = 0; nt < 8; ++nt) {
            const int n = wn * 64 + nt * 8 + g;
            const float* bp = sB + (kk + tig) * 136 + n;
            uint32_t b0 = cvt_tf32(bp[0]);
            uint32_t b1 = cvt_tf32(bp[4 * 136]);
            mma_tf32(acc[0][nt], a[0][0], a[0][1], a[0][2], a[0][3], b0, b1);
            mma_tf32(acc[1][nt], a[1][0], a[1][1], a[1][2], a[1][3], b0, b1);
        }
    }
}

template<bool RELU, bool HOUT>
__global__ void __launch_bounds__(256) mma_linear(
    const float* __restrict__ A, const float* __restrict__ W,
    const float* __restrict__ bias, void* __restrict__ Cv, int K, int N)
{
    extern __shared__ float sm[];
    float* sA = sm;
    float* sB = sm + 2 * ASZ;
    const int m0 = blockIdx.y << 7, n0 = blockIdx.x << 7;
    const uint32_t sa = smem_u32(sA), sb = smem_u32(sB);
    const float* Ab = A + (size_t)m0 * K;
    const float* Wb = W + n0;
    const int kiters = K >> 5;
    float acc[2][8][4] = {};
    load_A(sa, Ab, K, 0);
    load_B_n(sb, Wb, N, 0);
    cp_commit();
    for (int it = 0; it < kiters; ++it) {
        const int cur = it & 1, nxt = cur ^ 1;
        if (it + 1 < kiters) {
            load_A(sa + nxt * ASZ * 4, Ab, K, (it + 1) * 32);
            load_B_n(sb + nxt * (32 * 136) * 4, Wb, N, (it + 1) * 32);
        }
        cp_commit();
        cp_wait1();
        __syncthreads();
        compute_tile_lin(sA + cur * ASZ, sB + cur * 32 * 136, acc);
        __syncthreads();
    }
    const int lane = threadIdx.x & 31, warp = threadIdx.x >> 5;
    const int wm = warp >> 1, wn = warp & 1;
    const int g = lane >> 2, tig = lane & 3;
    #pragma unroll
    for (int mt = 0; mt < 2; ++mt)
        #pragma unroll
        for (int nt = 0; nt < 8; ++nt) {
            const int row = m0 + wm * 32 + mt * 16 + g;
            const int col = n0 + wn * 64 + nt * 8 + tig * 2;
            float2 bv = *(const float2*)(bias + col);
            float o0x = acc[mt][nt][0] + bv.x, o0y = acc[mt][nt][1] + bv.y;
            float o1x = acc[mt][nt][2] + bv.x, o1y = acc[mt][nt][3] + bv.y;
            if (RELU) {
                o0x = fmaxf(o0x, 0.f); o0y = fmaxf(o0y, 0.f);
                o1x = fmaxf(o1x, 0.f); o1y = fmaxf(o1y, 0.f);
            }
            if (HOUT) {
                __half* C = (__half*)Cv;
                *(__half2*)(C + (size_t)row * N + col) = __floats2half2_rn(o0x, o0y);
                *(__half2*)(C + (size_t)(row + 8) * N + col) = __floats2half2_rn(o1x, o1y);
            } else {
                float* C = (float*)Cv;
                *(float2*)(C + (size_t)row * N + col) = make_float2(o0x, o0y);
                *(float2*)(C + (size_t)(row + 8) * N + col) = make_float2(o1x, o1y);
            }
        }
}

// =================================================================
// V transpose + fp16 convert: g_v[b,s,h,d] -> g_vt[z][d][s]
// =================================================================
__global__ void __launch_bounds__(256) transpose_vh(
    const float* __restrict__ v, __half* __restrict__ vt)
{
    const int z = blockIdx.z, b = z >> 4, h = z & 15;
    const float* in = v + (size_t)b * SEQ * DIM + h * HDK;
    __half* out = vt + (size_t)z * HDK * SEQ;
    __shared__ float t[32][33];
    const int d0 = blockIdx.x * 32, s0 = blockIdx.y * 32;
    for (int i = threadIdx.y; i < 32; i += 8)
        t[i][threadIdx.x] = in[(size_t)(s0 + i) * DIM + d0 + threadIdx.x];
    __syncthreads();
    for (int i = threadIdx.y; i < 32; i += 8)
        out[(size_t)(d0 + i) * SEQ + s0 + threadIdx.x] = __float2half(t[threadIdx.x][i]);
}

// =================================================================
// Fused flash attention (fp16 mma, fp32 accum, online softmax).
// Block: 128 q-rows, 8 warps x 16 rows. K-tiles of 128.
// =================================================================
template<bool CAUSAL>
__global__ void __launch_bounds__(256, 2) flash_attn(
    const __half* __restrict__ qh, const __half* __restrict__ kh,
    const __half* __restrict__ vt, float* __restrict__ outm)
{
    const int z = blockIdx.y, b = z >> 4, h = z & 15;
    const int xt = CAUSAL ? ((int)gridDim.x - 1 - (int)blockIdx.x) : (int)blockIdx.x;
    const int m0 = xt << 7;
    extern __shared__ __half sh[];
    __half* sQ = sh;                       // 128 x QST
    __half* sK = sh + 128 * QST;           // 128 x KST
    __half* sV = sh + 2 * 128 * QST;       // HDK x VST  (rows = dk, cols = key)
    const int tid = threadIdx.x;
    const int wid = tid >> 5, lane = tid & 31;
    const int g = lane >> 2, tig = lane & 3;
    const uint32_t sq = smem_u32(sQ), sk = smem_u32(sK), sv = smem_u32(sV);

    // Q tile (loaded once)
    {
        const __half* src = qh + ((size_t)b * SEQ + m0) * DIM + h * HDK;
        #pragma unroll
        for (int j = 0; j < 4; ++j) {
            const int idx = tid + (j << 8);
            const int row = idx >> 3, c8 = (idx & 7) << 3;
            cp_async16(sq + (uint32_t)(row * QST + c8) * 2, src + (size_t)row * DIM + c8);
        }
    }

    float accO[8][4] = {};
    float mrow0 = -INFINITY, mrow1 = -INFINITY;
    float lrow0 = 0.f, lrow1 = 0.f;
    const int r0loc = wid * 16 + g;        // warp-local row (0..127)

    const int ntiles = CAUSAL ? (xt + 1) : (SEQ >> 7);
    for (int t = 0; t < ntiles; ++t) {
        const int n0 = t << 7;
        // K / Vt tiles
        {
            const __half* ks = kh + ((size_t)b * SEQ + n0) * DIM + h * HDK;
            #pragma unroll
            for (int j = 0; j < 4; ++j) {
                const int idx = tid + (j << 8);
                const int row = idx >> 3, c8 = (idx & 7) << 3;
                cp_async16(sk + (uint32_t)(row * KST + c8) * 2, ks + (size_t)row * DIM + c8);
            }
            const __half* vs = vt + (size_t)z * HDK * SEQ + n0;
            #pragma unroll
            for (int j = 0; j < 4; ++j) {
                const int idx = tid + (j << 8);
                const int row = idx >> 4, c8 = (idx & 15) << 3;
                cp_async16(sv + (uint32_t)(row * VST + c8) * 2, vs + (size_t)row * SEQ + c8);
            }
        }
        cp_commit();
        cp_wait0();
        __syncthreads();

        // ---- S = Q.K^T over this tile (16 n8-tiles) ----
        float accS[16][4];
        #pragma unroll
        for (int nt = 0; nt < 16; ++nt) {
            accS[nt][0] = 0.f; accS[nt][1] = 0.f; accS[nt][2] = 0.f; accS[nt][3] = 0.f;
        }
        #pragma unroll
        for (int ks = 0; ks < 4; ++ks) {
            const __half* ap = sQ + r0loc * QST + ks * 16 + 2 * tig;
            uint32_t a0 = *(const uint32_t*)(ap);
            uint32_t a1 = *(const uint32_t*)(ap + 8 * QST);
            uint32_t a2 = *(const uint32_t*)(ap + 8);
            uint32_t a3 = *(const uint32_t*)(ap + 8 * QST + 8);
            #pragma unroll
            for (int nt = 0; nt < 16; ++nt) {
                const __half* bp = sK + (nt * 8 + g) * KST + ks * 16 + 2 * tig;
                uint32_t b0 = *(const uint32_t*)(bp);
                uint32_t b1 = *(const uint32_t*)(bp + 8);
                mma_f16(accS[nt], a0, a1, a2, a3, b0, b1);
            }
        }

        // ---- scale + (diagonal) mask + row max ----
        float mn0 = mrow0, mn1 = mrow1;
        #pragma unroll
        for (int nt = 0; nt < 16; ++nt) {
            if (CAUSAL && n0 == m0) {
                const int col = nt * 8 + 2 * tig;
                if (col     > r0loc)     accS[nt][0] = -INFINITY;
                if (col + 1 > r0loc)     accS[nt][1] = -INFINITY;
                if (col     > r0loc + 8) accS[nt][2] = -INFINITY;
                if (col + 1 > r0loc + 8) accS[nt][3] = -INFINITY;
            }
            accS[nt][0] *= 0.125f; accS[nt][1] *= 0.125f;
            accS[nt][2] *= 0.125f; accS[nt][3] *= 0.125f;
            mn0 = fmaxf(mn0, fmaxf(accS[nt][0], accS[nt][1]));
            mn1 = fmaxf(mn1, fmaxf(accS[nt][2], accS[nt][3]));
        }
        mn0 = fmaxf(mn0, __shfl_xor_sync(0xFFFFFFFFu, mn0, 1));
        mn0 = fmaxf(mn0, __shfl_xor_sync(0xFFFFFFFFu, mn0, 2));
        mn1 = fmaxf(mn1, __shfl_xor_sync(0xFFFFFFFFu, mn1, 1));
        mn1 = fmaxf(mn1, __shfl_xor_sync(0xFFFFFFFFu, mn1, 2));
        const float cf0 = __expf(mrow0 - mn0);
        const float cf1 = __expf(mrow1 - mn1);
        mrow0 = mn0; mrow1 = mn1;
        #pragma unroll
        for (int nt = 0; nt < 8; ++nt) {
            accO[nt][0] *= cf0; accO[nt][1] *= cf0;
            accO[nt][2] *= cf1; accO[nt][3] *= cf1;
        }

        // ---- per-16-col chunk: exp -> pack -> PV mma (A = P from regs) ----
        float rs0 = 0.f, rs1 = 0.f;
        #pragma unroll
        for (int k2 = 0; k2 < 8; ++k2) {
            const float e00 = __expf(accS[2 * k2][0] - mn0);
            const float e01 = __expf(accS[2 * k2][1] - mn0);
            const float e02 = __expf(accS[2 * k2][2] - mn1);
            const float e03 = __expf(accS[2 * k2][3] - mn1);
            const float e10 = __expf(accS[2 * k2 + 1][0] - mn0);
            const float e11 = __expf(accS[2 * k2 + 1][1] - mn0);
            const float e12 = __expf(accS[2 * k2 + 1][2] - mn1);
            const float e13 = __expf(accS[2 * k2 + 1][3] - mn1);
            rs0 += e00 + e01 + e10 + e11;
            rs1 += e02 + e03 + e12 + e13;
            const uint32_t pa0 = pack_h2(e00, e01);
            const uint32_t pa1 = pack_h2(e02, e03);
            const uint32_t pa2 = pack_h2(e10, e11);
            const uint32_t pa3 = pack_h2(e12, e13);
            #pragma unroll
            for (int nt = 0; nt < 8; ++nt) {
                const __half* bp = sV + (nt * 8 + g) * VST + k2 * 16 + 2 * tig;
                uint32_t b0 = *(const uint32_t*)(bp);
                uint32_t b1 = *(const uint32_t*)(bp + 8);
                mma_f16(accO[nt], pa0, pa1, pa2, pa3, b0, b1);
            }
        }
        rs0 += __shfl_xor_sync(0xFFFFFFFFu, rs0, 1);
        rs0 += __shfl_xor_sync(0xFFFFFFFFu, rs0, 2);
        rs1 += __shfl_xor_sync(0xFFFFFFFFu, rs1, 1);
        rs1 += __shfl_xor_sync(0xFFFFFFFFu, rs1, 2);
        lrow0 = lrow0 * cf0 + rs0;
        lrow1 = lrow1 * cf1 + rs1;
        __syncthreads();   // smem reuse next iteration
    }

    // ---- epilogue ----
    const float inv0 = 1.f / lrow0, inv1 = 1.f / lrow1;
    const int row = m0 + r0loc;
    float* o0 = outm + ((size_t)b * SEQ + row) * DIM + h * HDK;
    #pragma unroll
    for (int nt = 0; nt < 8; ++nt) {
        const int col = nt * 8 + 2 * tig;
        *(float2*)(o0 + col) = make_float2(accO[nt][0] * inv0, accO[nt][1] * inv0);
        *(float2*)(o0 + 8 * DIM + col) = make_float2(accO[nt][2] * inv1, accO[nt][3] * inv1);
    }
}

// =================================================================
// Seq-norm (quirk: normalize over S, divide by unbiased VARIANCE)
// =================================================================
__global__ void __launch_bounds__(256) norm_stats_kernel(
    const float* __restrict__ x, const float* __restrict__ res,
    float* __restrict__ meanbuf, float* __restrict__ ivarbuf)
{
    const int d = blockIdx.x * 32 + threadIdx.x;
    const int b = blockIdx.y;
    double s1 = 0.0, s2 = 0.0;
    for (int s = threadIdx.y; s < SEQ; s += 8) {
        const size_t idx = ((size_t)b * SEQ + s) * DIM + d;
        const float vv = x[idx] + res[idx];
        s1 += vv;
        s2 += (double)vv * (double)vv;
    }
    __shared__ double sm1[8][32];
    __shared__ double sm2[8][32];
    sm1[threadIdx.y][threadIdx.x] = s1;
    sm2[threadIdx.y][threadIdx.x] = s2;
    __syncthreads();
    if (threadIdx.y == 0) {
        #pragma unroll
        for (int r = 1; r < 8; ++r) { s1 += sm1[r][threadIdx.x]; s2 += sm2[r][threadIdx.x]; }
        const double m   = s1 / (double)SEQ;
        const double var = (s2 - (double)SEQ * m * m) / (double)(SEQ - 1);
        meanbuf[b * DIM + d] = (float)m;
        ivarbuf[b * DIM + d] = (float)(1.0 / var);
    }
}

__global__ void __launch_bounds__(256) norm_apply_kernel(
    const float* __restrict__ x, const float* __restrict__ res,
    const float* __restrict__ meanbuf, const float* __restrict__ ivarbuf,
    float* __restrict__ out)
{
    const size_t idx = (size_t)blockIdx.x * 256 + threadIdx.x;
    const int d = (int)(idx & (DIM - 1));
    const int b = (int)(idx >> 21);
    const int c = b * DIM + d;
    out[idx] = (x[idx] + res[idx] - meanbuf[c]) * ivarbuf[c];
}

// =================================================================
// Host-side launcher
// =================================================================
extern "C" void kernel_launch(void* const* d_in, const int* in_sizes, int n_in,
                              void* d_out, int out_size)
{
    (void)in_sizes; (void)n_in; (void)out_size;
    const float* dec = (const float*)d_in[0];
    const float* enc = (const float*)d_in[1];
    const float* Wq1 = (const float*)d_in[2];
    const float* Wk1 = (const float*)d_in[3];
    const float* Wv1 = (const float*)d_in[4];
    const float* bq1 = (const float*)d_in[5];
    const float* bk1 = (const float*)d_in[6];
    const float* bv1 = (const float*)d_in[7];
    const float* Wq2 = (const float*)d_in[8];
    const float* Wk2 = (const float*)d_in[9];
    const float* Wv2 = (const float*)d_in[10];
    const float* bq2 = (const float*)d_in[11];
    const float* bk2 = (const float*)d_in[12];
    const float* bv2 = (const float*)d_in[13];
    const float* W1  = (const float*)d_in[14];
    const float* b1  = (const float*)d_in[15];
    const float* W2  = (const float*)d_in[16];
    const float* b2  = (const float*)d_in[17];
    float* out = (float*)d_out;

    float *v, *t0, *x1, *x2, *ffn, *mn, *iv;
    __half *qh, *kh, *vtb;
    cudaGetSymbolAddress((void**)&v,   g_v);
    cudaGetSymbolAddress((void**)&t0,  g_t0);
    cudaGetSymbolAddress((void**)&x1,  g_x1);
    cudaGetSymbolAddress((void**)&x2,  g_x2);
    cudaGetSymbolAddress((void**)&ffn, g_ffn);
    cudaGetSymbolAddress((void**)&mn,  g_mean);
    cudaGetSymbolAddress((void**)&iv,  g_ivar);
    cudaGetSymbolAddress((void**)&qh,  g_qh);
    cudaGetSymbolAddress((void**)&kh,  g_kh);
    cudaGetSymbolAddress((void**)&vtb, g_vt);

    const int SM_LIN = (2 * ASZ + 2 * 32 * 136) * 4;     // 71680 bytes
    cudaFuncSetAttribute(mma_linear<false, false>, cudaFuncAttributeMaxDynamicSharedMemorySize, SM_LIN);
    cudaFuncSetAttribute(mma_linear<false, true>,  cudaFuncAttributeMaxDynamicSharedMemorySize, SM_LIN);
    cudaFuncSetAttribute(mma_linear<true,  false>, cudaFuncAttributeMaxDynamicSharedMemorySize, SM_LIN);
    cudaFuncSetAttribute(flash_attn<true>,  cudaFuncAttributeMaxDynamicSharedMemorySize, FA_SMEM);
    cudaFuncSetAttribute(flash_attn<false>, cudaFuncAttributeMaxDynamicSharedMemorySize, FA_SMEM);

    const dim3 gProj(DIM / 128, MROWS / 128);            // (8, 32)
    const dim3 gFf1 (FFD / 128, MROWS / 128);            // (32, 32)
    const dim3 gTv  (HDK / 32, SEQ / 32, BH);            // (2, 64, 32)
    const dim3 gFA  (SEQ / 128, BH);                     // (16, 32)
    const dim3 bT(32, 8);
    const dim3 gSt(DIM / 32, BATCH);
    const int  nApply = (int)(((size_t)MROWS * DIM) / 256);

    // ---------- sublayer 1: causal self-attention ----------
    mma_linear<false, true ><<<gProj, 256, SM_LIN>>>(dec, Wq1, bq1, qh, DIM, DIM);
    mma_linear<false, true ><<<gProj, 256, SM_LIN>>>(dec, Wk1, bk1, kh, DIM, DIM);
    mma_linear<false, false><<<gProj, 256, SM_LIN>>>(dec, Wv1, bv1, v,  DIM, DIM);
    transpose_vh<<<gTv, bT>>>(v, vtb);
    flash_attn<true><<<gFA, 256, FA_SMEM>>>(qh, kh, vtb, t0);
    norm_stats_kernel<<<gSt, bT>>>(t0, dec, mn, iv);
    norm_apply_kernel<<<nApply, 256>>>(t0, dec, mn, iv, x1);

    // ---------- sublayer 2: cross-attention ----------
    mma_linear<false, true ><<<gProj, 256, SM_LIN>>>(x1,  Wq2, bq2, qh, DIM, DIM);
    mma_linear<false, true ><<<gProj, 256, SM_LIN>>>(enc, Wk2, bk2, kh, DIM, DIM);
    mma_linear<false, false><<<gProj, 256, SM_LIN>>>(enc, Wv2, bv2, v,  DIM, DIM);
    transpose_vh<<<gTv, bT>>>(v, vtb);
    flash_attn<false><<<gFA, 256, FA_SMEM>>>(qh, kh, vtb, t0);
    norm_stats_kernel<<<gSt, bT>>>(t0, x1, mn, iv);
    norm_apply_kernel<<<nApply, 256>>>(t0, x1, mn, iv, x2);

    // ---------- sublayer 3: FFN ----------
    mma_linear<true,  false><<<gFf1,  256, SM_LIN>>>(x2,  W1, b1, ffn, DIM, FFD);
    mma_linear<false, false><<<gProj, 256, SM_LIN>>>(ffn, W2, b2, t0,  FFD, DIM);
    norm_stats_kernel<<<gSt, bT>>>(t0, x2, mn, iv);
    norm_apply_kernel<<<nApply, 256>>>(t0, x2, mn, iv, out);
}

// round 7
// speedup vs baseline: 6.1376x; 1.4605x over previous
#include <cuda_runtime.h>
#include <cuda_fp16.h>
#include <cstdint>
#include <math.h>

// ---------------- problem constants ----------------
#define BATCH  2
#define SEQ    2048
#define DIM    1024
#define HEADS  16
#define HDK    64
#define FFD    4096
#define MROWS  (BATCH * SEQ)          // 4096
#define BH     (BATCH * HEADS)        // 32

// hgemm smem stride (halves): 64 + 8 pad; conflict-free fragment reads
#define HAST 72
#define HG_SMEM (4 * 128 * HAST * 2)  // 2 stages x (A+B), bytes = 73728

// flash smem strides (halves)
#define QST 72
#define KST 72
#define VST 136
#define FA_SMEM ((2 * 128 * QST + HDK * VST) * 2)   // 54272 bytes

// ---------------- device scratch ----------------
__device__ float  g_t0 [(size_t)MROWS * DIM];
__device__ float  g_x1 [(size_t)MROWS * DIM];
__device__ float  g_x2 [(size_t)MROWS * DIM];
__device__ __half g_dech[(size_t)MROWS * DIM];
__device__ __half g_ench[(size_t)MROWS * DIM];
__device__ __half g_x1h [(size_t)MROWS * DIM];
__device__ __half g_x2h [(size_t)MROWS * DIM];
__device__ __half g_ffnh[(size_t)MROWS * FFD];
__device__ __half g_qh [(size_t)MROWS * DIM];
__device__ __half g_kh [(size_t)MROWS * DIM];
__device__ __half g_vh [(size_t)MROWS * DIM];
__device__ __half g_vt [(size_t)BH * HDK * SEQ];
__device__ __half g_wth[6 * (size_t)DIM * DIM];     // transposed f16 proj weights
__device__ __half g_w1t[(size_t)FFD * DIM];
__device__ __half g_w2t[(size_t)DIM * FFD];

// ---------------- PTX helpers (sm_100 base target) ----------------
__device__ __forceinline__ uint32_t smem_u32(const void* p) {
    uint32_t a;
    asm("{ .reg .u64 t; cvta.to.shared.u64 t, %1; cvt.u32.u64 %0, t; }" : "=r"(a) : "l"(p));
    return a;
}
__device__ __forceinline__ void cp_async16(uint32_t saddr, const void* g) {
    asm volatile("cp.async.cg.shared.global [%0], [%1], 16;" :: "r"(saddr), "l"(g) : "memory");
}
__device__ __forceinline__ void cp_commit() {
    asm volatile("cp.async.commit_group;" ::: "memory");
}
__device__ __forceinline__ void cp_wait1() {
    asm volatile("cp.async.wait_group 1;" ::: "memory");
}
__device__ __forceinline__ void cp_wait0() {
    asm volatile("cp.async.wait_group 0;" ::: "memory");
}
__device__ __forceinline__ void mma_f16(float c[4],
    uint32_t a0, uint32_t a1, uint32_t a2, uint32_t a3, uint32_t b0, uint32_t b1) {
    asm volatile(
        "mma.sync.aligned.m16n8k16.row.col.f32.f16.f16.f32 "
        "{%0,%1,%2,%3}, {%4,%5,%6,%7}, {%8,%9}, {%0,%1,%2,%3};"
        : "+f"(c[0]), "+f"(c[1]), "+f"(c[2]), "+f"(c[3])
        : "r"(a0), "r"(a1), "r"(a2), "r"(a3), "r"(b0), "r"(b1));
}
__device__ __forceinline__ uint32_t pack_h2(float x, float y) {
    __half2 h = __floats2half2_rn(x, y);
    return *(uint32_t*)&h;
}

// =================================================================
// Converters
// =================================================================
__global__ void __launch_bounds__(256) cvt_act(const float* __restrict__ in,
                                               __half* __restrict__ out)
{
    const size_t i = ((size_t)blockIdx.x * 256 + threadIdx.x) * 4;
    float4 v = *(const float4*)(in + i);
    __half2 h0 = __floats2half2_rn(v.x, v.y);
    __half2 h1 = __floats2half2_rn(v.z, v.w);
    *(__half2*)(out + i) = h0;
    *(__half2*)(out + i + 2) = h1;
}

// W[K,N] f32 -> Wt[N,K] f16 (tiled transpose)
__global__ void __launch_bounds__(256) cvt_w_t(const float* __restrict__ in,
                                               __half* __restrict__ out, int K, int N)
{
    __shared__ float t[32][33];
    const int n0 = blockIdx.x * 32, k0 = blockIdx.y * 32;
    for (int i = threadIdx.y; i < 32; i += 8)
        t[i][threadIdx.x] = in[(size_t)(k0 + i) * N + n0 + threadIdx.x];
    __syncthreads();
    for (int i = threadIdx.y; i < 32; i += 8)
        out[(size_t)(n0 + i) * K + k0 + threadIdx.x] = __float2half(t[threadIdx.x][i]);
}

// vh[b,s,h,d] f16 -> vt[z][d][s] f16
__global__ void __launch_bounds__(256) transpose_vh(
    const __half* __restrict__ vh, __half* __restrict__ vt)
{
    const int z = blockIdx.z, b = z >> 4, h = z & 15;
    const __half* in = vh + (size_t)b * SEQ * DIM + h * HDK;
    __half* out = vt + (size_t)z * HDK * SEQ;
    __shared__ __half t[32][34];
    const int d0 = blockIdx.x * 32, s0 = blockIdx.y * 32;
    for (int i = threadIdx.y; i < 32; i += 8)
        t[i][threadIdx.x] = in[(size_t)(s0 + i) * DIM + d0 + threadIdx.x];
    __syncthreads();
    for (int i = threadIdx.y; i < 32; i += 8)
        out[(size_t)(d0 + i) * SEQ + s0 + threadIdx.x] = t[threadIdx.x][i];
}

// =================================================================
// fp16 HGEMM: C[M,N] = A[M,K] @ Bt[N,K]^T + bias. 128x128x64 tiles.
// =================================================================
__device__ __forceinline__ void hload(uint32_t sbase, const __half* G, int ldg, int k0) {
    const int t = threadIdx.x;
    #pragma unroll
    for (int j = 0; j < 4; ++j) {                 // 128 x 64 halves
        const int idx = t + (j << 8);
        const int row = idx >> 3, c8 = (idx & 7) << 3;
        cp_async16(sbase + (uint32_t)(row * HAST + c8) * 2, G + (size_t)row * ldg + k0 + c8);
    }
}

template<bool RELU, bool HOUT>
__global__ void __launch_bounds__(256) hgemm(
    const __half* __restrict__ A, const __half* __restrict__ Bt,
    const float* __restrict__ bias, void* __restrict__ Cv, int K, int N)
{
    extern __shared__ __half sh[];
    __half* sA = sh;                      // 2 stages x 128 x HAST
    __half* sB = sh + 2 * 128 * HAST;
    const int m0 = blockIdx.y << 7, n0 = blockIdx.x << 7;
    const uint32_t sa = smem_u32(sA), sb = smem_u32(sB);
    const __half* Ab = A + (size_t)m0 * K;
    const __half* Bb = Bt + (size_t)n0 * K;
    const int kiters = K >> 6;
    const int lane = threadIdx.x & 31, warp = threadIdx.x >> 5;
    const int wm = warp >> 1, wn = warp & 1;
    const int g = lane >> 2, tig = lane & 3;
    constexpr uint32_t STG = 128 * HAST * 2;   // stage stride bytes

    float acc[2][8][4] = {};
    hload(sa, Ab, K, 0);
    hload(sb, Bb, K, 0);
    cp_commit();
    for (int it = 0; it < kiters; ++it) {
        const int cur = it & 1, nxt = cur ^ 1;
        if (it + 1 < kiters) {
            hload(sa + nxt * STG, Ab, K, (it + 1) << 6);
            hload(sb + nxt * STG, Bb, K, (it + 1) << 6);
        }
        cp_commit();
        cp_wait1();
        __syncthreads();
        const __half* cA = sA + cur * 128 * HAST;
        const __half* cB = sB + cur * 128 * HAST;
        #pragma unroll
        for (int ks = 0; ks < 4; ++ks) {
            const int kk = ks << 4;
            uint32_t a[2][4];
            #pragma unroll
            for (int mt = 0; mt < 2; ++mt) {
                const __half* ap = cA + (wm * 32 + mt * 16 + g) * HAST + kk + 2 * tig;
                a[mt][0] = *(const uint32_t*)(ap);
                a[mt][1] = *(const uint32_t*)(ap + 8 * HAST);
                a[mt][2] = *(const uint32_t*)(ap + 8);
                a[mt][3] = *(const uint32_t*)(ap + 8 * HAST + 8);
            }
            #pragma unroll
            for (int nt = 0; nt < 8; ++nt) {
                const __half* bp = cB + (wn * 64 + nt * 8 + g) * HAST + kk + 2 * tig;
                uint32_t b0 = *(const uint32_t*)(bp);
                uint32_t b1 = *(const uint32_t*)(bp + 8);
                mma_f16(acc[0][nt], a[0][0], a[0][1], a[0][2], a[0][3], b0, b1);
                mma_f16(acc[1][nt], a[1][0], a[1][1], a[1][2], a[1][3], b0, b1);
            }
        }
        __syncthreads();
    }
    #pragma unroll
    for (int mt = 0; mt < 2; ++mt)
        #pragma unroll
        for (int nt = 0; nt < 8; ++nt) {
            const int row = m0 + wm * 32 + mt * 16 + g;
            const int col = n0 + wn * 64 + nt * 8 + tig * 2;
            float2 bv = *(const float2*)(bias + col);
            float o0x = acc[mt][nt][0] + bv.x, o0y = acc[mt][nt][1] + bv.y;
            float o1x = acc[mt][nt][2] + bv.x, o1y = acc[mt][nt][3] + bv.y;
            if (RELU) {
                o0x = fmaxf(o0x, 0.f); o0y = fmaxf(o0y, 0.f);
                o1x = fmaxf(o1x, 0.f); o1y = fmaxf(o1y, 0.f);
            }
            if (HOUT) {
                __half* C = (__half*)Cv;
                *(__half2*)(C + (size_t)row * N + col) = __floats2half2_rn(o0x, o0y);
                *(__half2*)(C + (size_t)(row + 8) * N + col) = __floats2half2_rn(o1x, o1y);
            } else {
                float* C = (float*)Cv;
                *(float2*)(C + (size_t)row * N + col) = make_float2(o0x, o0y);
                *(float2*)(C + (size_t)(row + 8) * N + col) = make_float2(o1x, o1y);
            }
        }
}

// =================================================================
// Fused flash attention (fp16 mma, fp32 accum, online softmax).
// =================================================================
template<bool CAUSAL>
__global__ void __launch_bounds__(256, 2) flash_attn(
    const __half* __restrict__ qh, const __half* __restrict__ kh,
    const __half* __restrict__ vt, float* __restrict__ outm)
{
    const int z = blockIdx.y, b = z >> 4, h = z & 15;
    const int xt = CAUSAL ? ((int)gridDim.x - 1 - (int)blockIdx.x) : (int)blockIdx.x;
    const int m0 = xt << 7;
    extern __shared__ __half sh[];
    __half* sQ = sh;
    __half* sK = sh + 128 * QST;
    __half* sV = sh + 2 * 128 * QST;
    const int tid = threadIdx.x;
    const int wid = tid >> 5, lane = tid & 31;
    const int g = lane >> 2, tig = lane & 3;
    const uint32_t sq = smem_u32(sQ), sk = smem_u32(sK), sv = smem_u32(sV);

    {
        const __half* src = qh + ((size_t)b * SEQ + m0) * DIM + h * HDK;
        #pragma unroll
        for (int j = 0; j < 4; ++j) {
            const int idx = tid + (j << 8);
            const int row = idx >> 3, c8 = (idx & 7) << 3;
            cp_async16(sq + (uint32_t)(row * QST + c8) * 2, src + (size_t)row * DIM + c8);
        }
    }

    float accO[8][4] = {};
    float mrow0 = -INFINITY, mrow1 = -INFINITY;
    float lrow0 = 0.f, lrow1 = 0.f;
    const int r0loc = wid * 16 + g;

    const int ntiles = CAUSAL ? (xt + 1) : (SEQ >> 7);
    for (int t = 0; t < ntiles; ++t) {
        const int n0 = t << 7;
        {
            const __half* ks = kh + ((size_t)b * SEQ + n0) * DIM + h * HDK;
            #pragma unroll
            for (int j = 0; j < 4; ++j) {
                const int idx = tid + (j << 8);
                const int row = idx >> 3, c8 = (idx & 7) << 3;
                cp_async16(sk + (uint32_t)(row * KST + c8) * 2, ks + (size_t)row * DIM + c8);
            }
            const __half* vs = vt + (size_t)z * HDK * SEQ + n0;
            #pragma unroll
            for (int j = 0; j < 4; ++j) {
                const int idx = tid + (j << 8);
                const int row = idx >> 4, c8 = (idx & 15) << 3;
                cp_async16(sv + (uint32_t)(row * VST + c8) * 2, vs + (size_t)row * SEQ + c8);
            }
        }
        cp_commit();
        cp_wait0();
        __syncthreads();

        float accS[16][4];
        #pragma unroll
        for (int nt = 0; nt < 16; ++nt) {
            accS[nt][0] = 0.f; accS[nt][1] = 0.f; accS[nt][2] = 0.f; accS[nt][3] = 0.f;
        }
        #pragma unroll
        for (int ks = 0; ks < 4; ++ks) {
            const __half* ap = sQ + r0loc * QST + ks * 16 + 2 * tig;
            uint32_t a0 = *(const uint32_t*)(ap);
            uint32_t a1 = *(const uint32_t*)(ap + 8 * QST);
            uint32_t a2 = *(const uint32_t*)(ap + 8);
            uint32_t a3 = *(const uint32_t*)(ap + 8 * QST + 8);
            #pragma unroll
            for (int nt = 0; nt < 16; ++nt) {
                const __half* bp = sK + (nt * 8 + g) * KST + ks * 16 + 2 * tig;
                uint32_t b0 = *(const uint32_t*)(bp);
                uint32_t b1 = *(const uint32_t*)(bp + 8);
                mma_f16(accS[nt], a0, a1, a2, a3, b0, b1);
            }
        }

        float mn0 = mrow0, mn1 = mrow1;
        #pragma unroll
        for (int nt = 0; nt < 16; ++nt) {
            if (CAUSAL && n0 == m0) {
                const int col = nt * 8 + 2 * tig;
                if (col     > r0loc)     accS[nt][0] = -INFINITY;
                if (col + 1 > r0loc)     accS[nt][1] = -INFINITY;
                if (col     > r0loc + 8) accS[nt][2] = -INFINITY;
                if (col + 1 > r0loc + 8) accS[nt][3] = -INFINITY;
            }
            accS[nt][0] *= 0.125f; accS[nt][1] *= 0.125f;
            accS[nt][2] *= 0.125f; accS[nt][3] *= 0.125f;
            mn0 = fmaxf(mn0, fmaxf(accS[nt][0], accS[nt][1]));
            mn1 = fmaxf(mn1, fmaxf(accS[nt][2], accS[nt][3]));
        }
        mn0 = fmaxf(mn0, __shfl_xor_sync(0xFFFFFFFFu, mn0, 1));
        mn0 = fmaxf(mn0, __shfl_xor_sync(0xFFFFFFFFu, mn0, 2));
        mn1 = fmaxf(mn1, __shfl_xor_sync(0xFFFFFFFFu, mn1, 1));
        mn1 = fmaxf(mn1, __shfl_xor_sync(0xFFFFFFFFu, mn1, 2));
        const float cf0 = __expf(mrow0 - mn0);
        const float cf1 = __expf(mrow1 - mn1);
        mrow0 = mn0; mrow1 = mn1;
        #pragma unroll
        for (int nt = 0; nt < 8; ++nt) {
            accO[nt][0] *= cf0; accO[nt][1] *= cf0;
            accO[nt][2] *= cf1; accO[nt][3] *= cf1;
        }

        float rs0 = 0.f, rs1 = 0.f;
        #pragma unroll
        for (int k2 = 0; k2 < 8; ++k2) {
            const float e00 = __expf(accS[2 * k2][0] - mn0);
            const float e01 = __expf(accS[2 * k2][1] - mn0);
            const float e02 = __expf(accS[2 * k2][2] - mn1);
            const float e03 = __expf(accS[2 * k2][3] - mn1);
            const float e10 = __expf(accS[2 * k2 + 1][0] - mn0);
            const float e11 = __expf(accS[2 * k2 + 1][1] - mn0);
            const float e12 = __expf(accS[2 * k2 + 1][2] - mn1);
            const float e13 = __expf(accS[2 * k2 + 1][3] - mn1);
            rs0 += e00 + e01 + e10 + e11;
            rs1 += e02 + e03 + e12 + e13;
            const uint32_t pa0 = pack_h2(e00, e01);
            const uint32_t pa1 = pack_h2(e02, e03);
            const uint32_t pa2 = pack_h2(e10, e11);
            const uint32_t pa3 = pack_h2(e12, e13);
            #pragma unroll
            for (int nt = 0; nt < 8; ++nt) {
                const __half* bp = sV + (nt * 8 + g) * VST + k2 * 16 + 2 * tig;
                uint32_t b0 = *(const uint32_t*)(bp);
                uint32_t b1 = *(const uint32_t*)(bp + 8);
                mma_f16(accO[nt], pa0, pa1, pa2, pa3, b0, b1);
            }
        }
        rs0 += __shfl_xor_sync(0xFFFFFFFFu, rs0, 1);
        rs0 += __shfl_xor_sync(0xFFFFFFFFu, rs0, 2);
        rs1 += __shfl_xor_sync(0xFFFFFFFFu, rs1, 1);
        rs1 += __shfl_xor_sync(0xFFFFFFFFu, rs1, 2);
        lrow0 = lrow0 * cf0 + rs0;
        lrow1 = lrow1 * cf1 + rs1;
        __syncthreads();
    }

    const float inv0 = 1.f / lrow0, inv1 = 1.f / lrow1;
    const int row = m0 + r0loc;
    float* o0 = outm + ((size_t)b * SEQ + row) * DIM + h * HDK;
    #pragma unroll
    for (int nt = 0; nt < 8; ++nt) {
        const int col = nt * 8 + 2 * tig;
        *(float2*)(o0 + col) = make_float2(accO[nt][0] * inv0, accO[nt][1] * inv0);
        *(float2*)(o0 + 8 * DIM + col) = make_float2(accO[nt][2] * inv1, accO[nt][3] * inv1);
    }
}

// =================================================================
// Fused seq-norm (quirk: normalize over S, divide by unbiased VARIANCE)
// block (16,16): 16 d-cols, 16 seq-threads. Stats (f64) then apply.
// =================================================================
template<bool HOUT>
__global__ void __launch_bounds__(256) seq_norm(
    const float* __restrict__ x, const float* __restrict__ res,
    float* __restrict__ out, __half* __restrict__ outh)
{
    const int d = blockIdx.x * 16 + threadIdx.x;
    const int b = blockIdx.y;
    const int ty = threadIdx.y;
    double s1 = 0.0, s2 = 0.0;
    for (int s = ty; s < SEQ; s += 16) {
        const size_t idx = ((size_t)b * SEQ + s) * DIM + d;
        const float vv = x[idx] + res[idx];
        s1 += vv;
        s2 += (double)vv * (double)vv;
    }
    __shared__ double sm1[16][16];
    __shared__ double sm2[16][16];
    __shared__ float smean[16], sivar[16];
    sm1[ty][threadIdx.x] = s1;
    sm2[ty][threadIdx.x] = s2;
    __syncthreads();
    if (ty == 0) {
        #pragma unroll
        for (int r = 1; r < 16; ++r) { s1 += sm1[r][threadIdx.x]; s2 += sm2[r][threadIdx.x]; }
        const double m   = s1 / (double)SEQ;
        const double var = (s2 - (double)SEQ * m * m) / (double)(SEQ - 1);
        smean[threadIdx.x] = (float)m;
        sivar[threadIdx.x] = (float)(1.0 / var);
    }
    __syncthreads();
    const float m = smean[threadIdx.x], ivr = sivar[threadIdx.x];
    for (int s = ty; s < SEQ; s += 16) {
        const size_t idx = ((size_t)b * SEQ + s) * DIM + d;
        const float o = (x[idx] + res[idx] - m) * ivr;
        out[idx] = o;
        if (HOUT) outh[idx] = __float2half(o);
    }
}

// =================================================================
// Host-side launcher
// =================================================================
extern "C" void kernel_launch(void* const* d_in, const int* in_sizes, int n_in,
                              void* d_out, int out_size)
{
    (void)in_sizes; (void)n_in; (void)out_size;
    const float* dec = (const float*)d_in[0];
    const float* enc = (const float*)d_in[1];
    const float* Wq1 = (const float*)d_in[2];
    const float* Wk1 = (const float*)d_in[3];
    const float* Wv1 = (const float*)d_in[4];
    const float* bq1 = (const float*)d_in[5];
    const float* bk1 = (const float*)d_in[6];
    const float* bv1 = (const float*)d_in[7];
    const float* Wq2 = (const float*)d_in[8];
    const float* Wk2 = (const float*)d_in[9];
    const float* Wv2 = (const float*)d_in[10];
    const float* bq2 = (const float*)d_in[11];
    const float* bk2 = (const float*)d_in[12];
    const float* bv2 = (const float*)d_in[13];
    const float* W1  = (const float*)d_in[14];
    const float* b1  = (const float*)d_in[15];
    const float* W2  = (const float*)d_in[16];
    const float* b2  = (const float*)d_in[17];
    float* out = (float*)d_out;

    float *t0, *x1, *x2;
    __half *dech, *ench, *x1h, *x2h, *ffnh, *qh, *kh, *vh, *vtb, *wth, *w1t, *w2t;
    cudaGetSymbolAddress((void**)&t0,   g_t0);
    cudaGetSymbolAddress((void**)&x1,   g_x1);
    cudaGetSymbolAddress((void**)&x2,   g_x2);
    cudaGetSymbolAddress((void**)&dech, g_dech);
    cudaGetSymbolAddress((void**)&ench, g_ench);
    cudaGetSymbolAddress((void**)&x1h,  g_x1h);
    cudaGetSymbolAddress((void**)&x2h,  g_x2h);
    cudaGetSymbolAddress((void**)&ffnh, g_ffnh);
    cudaGetSymbolAddress((void**)&qh,   g_qh);
    cudaGetSymbolAddress((void**)&kh,   g_kh);
    cudaGetSymbolAddress((void**)&vh,   g_vh);
    cudaGetSymbolAddress((void**)&vtb,  g_vt);
    cudaGetSymbolAddress((void**)&wth,  g_wth);
    cudaGetSymbolAddress((void**)&w1t,  g_w1t);
    cudaGetSymbolAddress((void**)&w2t,  g_w2t);
    __half* wq1t = wth + 0 * (size_t)DIM * DIM;
    __half* wk1t = wth + 1 * (size_t)DIM * DIM;
    __half* wv1t = wth + 2 * (size_t)DIM * DIM;
    __half* wq2t = wth + 3 * (size_t)DIM * DIM;
    __half* wk2t = wth + 4 * (size_t)DIM * DIM;
    __half* wv2t = wth + 5 * (size_t)DIM * DIM;

    cudaFuncSetAttribute(hgemm<false, false>, cudaFuncAttributeMaxDynamicSharedMemorySize, HG_SMEM);
    cudaFuncSetAttribute(hgemm<false, true>,  cudaFuncAttributeMaxDynamicSharedMemorySize, HG_SMEM);
    cudaFuncSetAttribute(hgemm<true,  true>,  cudaFuncAttributeMaxDynamicSharedMemorySize, HG_SMEM);
    cudaFuncSetAttribute(flash_attn<true>,  cudaFuncAttributeMaxDynamicSharedMemorySize, FA_SMEM);
    cudaFuncSetAttribute(flash_attn<false>, cudaFuncAttributeMaxDynamicSharedMemorySize, FA_SMEM);

    const dim3 bT(32, 8);
    const dim3 gWsq(DIM / 32, DIM / 32);
    const dim3 gW1 (FFD / 32, DIM / 32);
    const dim3 gW2 (DIM / 32, FFD / 32);
    const dim3 gProj(DIM / 128, MROWS / 128);
    const dim3 gFf1 (FFD / 128, MROWS / 128);
    const dim3 gTv  (HDK / 32, SEQ / 32, BH);
    const dim3 gFA  (SEQ / 128, BH);
    const dim3 gNorm(DIM / 16, BATCH);
    const dim3 bNorm(16, 16);
    const int  nCvt = (int)(((size_t)MROWS * DIM) / 1024);

    // ---------- weight + input conversion ----------
    cvt_w_t<<<gWsq, bT>>>(Wq1, wq1t, DIM, DIM);
    cvt_w_t<<<gWsq, bT>>>(Wk1, wk1t, DIM, DIM);
    cvt_w_t<<<gWsq, bT>>>(Wv1, wv1t, DIM, DIM);
    cvt_w_t<<<gWsq, bT>>>(Wq2, wq2t, DIM, DIM);
    cvt_w_t<<<gWsq, bT>>>(Wk2, wk2t, DIM, DIM);
    cvt_w_t<<<gWsq, bT>>>(Wv2, wv2t, DIM, DIM);
    cvt_w_t<<<gW1,  bT>>>(W1,  w1t,  DIM, FFD);
    cvt_w_t<<<gW2,  bT>>>(W2,  w2t,  FFD, DIM);
    cvt_act<<<nCvt, 256>>>(dec, dech);
    cvt_act<<<nCvt, 256>>>(enc, ench);

    // ---------- sublayer 1: causal self-attention ----------
    hgemm<false, true><<<gProj, 256, HG_SMEM>>>(dech, wq1t, bq1, qh, DIM, DIM);
    hgemm<false, true><<<gProj, 256, HG_SMEM>>>(dech, wk1t, bk1, kh, DIM, DIM);
    hgemm<false, true><<<gProj, 256, HG_SMEM>>>(dech, wv1t, bv1, vh, DIM, DIM);
    transpose_vh<<<gTv, bT>>>(vh, vtb);
    flash_attn<true><<<gFA, 256, FA_SMEM>>>(qh, kh, vtb, t0);
    seq_norm<true><<<gNorm, bNorm>>>(t0, dec, x1, x1h);

    // ---------- sublayer 2: cross-attention ----------
    hgemm<false, true><<<gProj, 256, HG_SMEM>>>(x1h,  wq2t, bq2, qh, DIM, DIM);
    hgemm<false, true><<<gProj, 256, HG_SMEM>>>(ench, wk2t, bk2, kh, DIM, DIM);
    hgemm<false, true><<<gProj, 256, HG_SMEM>>>(ench, wv2t, bv2, vh, DIM, DIM);
    transpose_vh<<<gTv, bT>>>(vh, vtb);
    flash_attn<false><<<gFA, 256, FA_SMEM>>>(qh, kh, vtb, t0);
    seq_norm<true><<<gNorm, bNorm>>>(t0, x1, x2, x2h);

    // ---------- sublayer 3: FFN ----------
    hgemm<true,  true ><<<gFf1,  256, HG_SMEM>>>(x2h,  w1t, b1, ffnh, DIM, FFD);
    hgemm<false, false><<<gProj, 256, HG_SMEM>>>(ffnh, w2t, b2, t0,   FFD, DIM);
    seq_norm<false><<<gNorm, bNorm>>>(t0, x2, out, nullptr);
}

// round 8
// speedup vs baseline: 6.5134x; 1.0612x over previous
#include <cuda_runtime.h>
#include <cuda_fp16.h>
#include <cstdint>
#include <math.h>

// ---------------- problem constants ----------------
#define BATCH  2
#define SEQ    2048
#define DIM    1024
#define HEADS  16
#define HDK    64
#define FFD    4096
#define MROWS  (BATCH * SEQ)          // 4096
#define BH     (BATCH * HEADS)        // 32

// hgemm smem stride (halves): 64 + 8 pad; conflict-free fragment reads
#define HAST 72
#define HG_SMEM (4 * 128 * HAST * 2)  // 2 stages x (A+B), bytes = 73728

// flash smem strides (halves)
#define QST 72
#define KST 72
#define VST 136
#define FA_SMEM ((2 * 128 * QST + HDK * VST) * 2)   // 54272 bytes

// ---------------- device scratch ----------------
__device__ float  g_t0 [(size_t)MROWS * DIM];
__device__ float  g_x1 [(size_t)MROWS * DIM];
__device__ float  g_x2 [(size_t)MROWS * DIM];
__device__ __half g_dech[(size_t)MROWS * DIM];
__device__ __half g_ench[(size_t)MROWS * DIM];
__device__ __half g_x1h [(size_t)MROWS * DIM];
__device__ __half g_x2h [(size_t)MROWS * DIM];
__device__ __half g_ffnh[(size_t)MROWS * FFD];
__device__ __half g_qkvh[(size_t)MROWS * 3 * DIM];  // fused QKV / KV outputs
__device__ __half g_qh  [(size_t)MROWS * DIM];      // sublayer2 Q
__device__ __half g_vt [(size_t)BH * HDK * SEQ];
__device__ __half g_wth[6 * (size_t)DIM * DIM];     // transposed f16 proj weights (contiguous)
__device__ __half g_w1t[(size_t)FFD * DIM];
__device__ __half g_w2t[(size_t)DIM * FFD];
__device__ float  g_bias3[3 * DIM];                 // concat bias qkv / kv

// ---------------- PTX helpers (sm_100 base target) ----------------
__device__ __forceinline__ uint32_t smem_u32(const void* p) {
    uint32_t a;
    asm("{ .reg .u64 t; cvta.to.shared.u64 t, %1; cvt.u32.u64 %0, t; }" : "=r"(a) : "l"(p));
    return a;
}
__device__ __forceinline__ void cp_async16(uint32_t saddr, const void* g) {
    asm volatile("cp.async.cg.shared.global [%0], [%1], 16;" :: "r"(saddr), "l"(g) : "memory");
}
__device__ __forceinline__ void cp_commit() {
    asm volatile("cp.async.commit_group;" ::: "memory");
}
__device__ __forceinline__ void cp_wait1() {
    asm volatile("cp.async.wait_group 1;" ::: "memory");
}
__device__ __forceinline__ void cp_wait0() {
    asm volatile("cp.async.wait_group 0;" ::: "memory");
}
__device__ __forceinline__ void mma_f16(float c[4],
    uint32_t a0, uint32_t a1, uint32_t a2, uint32_t a3, uint32_t b0, uint32_t b1) {
    asm volatile(
        "mma.sync.aligned.m16n8k16.row.col.f32.f16.f16.f32 "
        "{%0,%1,%2,%3}, {%4,%5,%6,%7}, {%8,%9}, {%0,%1,%2,%3};"
        : "+f"(c[0]), "+f"(c[1]), "+f"(c[2]), "+f"(c[3])
        : "r"(a0), "r"(a1), "r"(a2), "r"(a3), "r"(b0), "r"(b1));
}
__device__ __forceinline__ void ldm_x4(uint32_t& r0, uint32_t& r1, uint32_t& r2, uint32_t& r3,
                                       uint32_t addr) {
    asm volatile("ldmatrix.sync.aligned.m8n8.x4.shared.b16 {%0,%1,%2,%3}, [%4];"
                 : "=r"(r0), "=r"(r1), "=r"(r2), "=r"(r3) : "r"(addr));
}
__device__ __forceinline__ uint32_t pack_h2(float x, float y) {
    __half2 h = __floats2half2_rn(x, y);
    return *(uint32_t*)&h;
}

// =================================================================
// Converters
// =================================================================
__global__ void __launch_bounds__(256) cvt_act(const float* __restrict__ in,
                                               __half* __restrict__ out)
{
    const size_t i = ((size_t)blockIdx.x * 256 + threadIdx.x) * 4;
    float4 v = *(const float4*)(in + i);
    *(__half2*)(out + i) = __floats2half2_rn(v.x, v.y);
    *(__half2*)(out + i + 2) = __floats2half2_rn(v.z, v.w);
}

// W[K,N] f32 -> Wt[N,K] f16 (tiled transpose)
__global__ void __launch_bounds__(256) cvt_w_t(const float* __restrict__ in,
                                               __half* __restrict__ out, int K, int N)
{
    __shared__ float t[32][33];
    const int n0 = blockIdx.x * 32, k0 = blockIdx.y * 32;
    for (int i = threadIdx.y; i < 32; i += 8)
        t[i][threadIdx.x] = in[(size_t)(k0 + i) * N + n0 + threadIdx.x];
    __syncthreads();
    for (int i = threadIdx.y; i < 32; i += 8)
        out[(size_t)(n0 + i) * K + k0 + threadIdx.x] = __float2half(t[threadIdx.x][i]);
}

__global__ void __launch_bounds__(256) concat_bias3(
    const float* __restrict__ b0, const float* __restrict__ b1,
    const float* __restrict__ b2, float* __restrict__ out, int n)
{
    const int i = blockIdx.x * 256 + threadIdx.x;
    if (i >= n * DIM) return;
    const int seg = i >> 10, off = i & (DIM - 1);
    const float* src = (seg == 0) ? b0 : (seg == 1) ? b1 : b2;
    out[i] = src[off];
}

// vh[b,s,h,d] (row stride ldv) f16 -> vt[z][d][s] f16
__global__ void __launch_bounds__(256) transpose_vh(
    const __half* __restrict__ vh, int ldv, __half* __restrict__ vt)
{
    const int z = blockIdx.z, b = z >> 4, h = z & 15;
    const __half* in = vh + (size_t)b * SEQ * ldv + h * HDK;
    __half* out = vt + (size_t)z * HDK * SEQ;
    __shared__ __half t[32][34];
    const int d0 = blockIdx.x * 32, s0 = blockIdx.y * 32;
    for (int i = threadIdx.y; i < 32; i += 8)
        t[i][threadIdx.x] = in[(size_t)(s0 + i) * ldv + d0 + threadIdx.x];
    __syncthreads();
    for (int i = threadIdx.y; i < 32; i += 8)
        out[(size_t)(d0 + i) * SEQ + s0 + threadIdx.x] = t[threadIdx.x][i];
}

// =================================================================
// fp16 HGEMM: C[M,N] = A[M,K] @ Bt[N,K]^T + bias. 128x128x64 tiles.
// ldc = output row stride (enables fused-QKV packed outputs).
// =================================================================
__device__ __forceinline__ void hload(uint32_t sbase, const __half* G, int ldg, int k0) {
    const int t = threadIdx.x;
    #pragma unroll
    for (int j = 0; j < 4; ++j) {                 // 128 x 64 halves
        const int idx = t + (j << 8);
        const int row = idx >> 3, c8 = (idx & 7) << 3;
        cp_async16(sbase + (uint32_t)(row * HAST + c8) * 2, G + (size_t)row * ldg + k0 + c8);
    }
}

template<bool RELU, bool HOUT>
__global__ void __launch_bounds__(256) hgemm(
    const __half* __restrict__ A, const __half* __restrict__ Bt,
    const float* __restrict__ bias, void* __restrict__ Cv, int K, int ldc)
{
    extern __shared__ __half sh[];
    __half* sA = sh;                      // 2 stages x 128 x HAST
    __half* sB = sh + 2 * 128 * HAST;
    const int m0 = blockIdx.y << 7, n0 = blockIdx.x << 7;
    const uint32_t sa = smem_u32(sA), sb = smem_u32(sB);
    const __half* Ab = A + (size_t)m0 * K;
    const __half* Bb = Bt + (size_t)n0 * K;
    const int kiters = K >> 6;
    const int lane = threadIdx.x & 31, warp = threadIdx.x >> 5;
    const int wm = warp >> 1, wn = warp & 1;
    const int g = lane >> 2, tig = lane & 3;
    constexpr uint32_t STG = 128 * HAST * 2;   // stage stride bytes

    // per-lane ldmatrix offsets (bytes, relative to stage base)
    const uint32_t aoff = (uint32_t)(((wm * 32 + (lane & 15)) * HAST + ((lane >> 4) << 3)) * 2);
    const uint32_t boff = (uint32_t)(((wn * 64 + (lane & 7) + ((lane >> 4) << 3)) * HAST + (lane & 8)) * 2);

    float acc[2][8][4] = {};
    hload(sa, Ab, K, 0);
    hload(sb, Bb, K, 0);
    cp_commit();
    for (int it = 0; it < kiters; ++it) {
        const int cur = it & 1, nxt = cur ^ 1;
        if (it + 1 < kiters) {
            hload(sa + nxt * STG, Ab, K, (it + 1) << 6);
            hload(sb + nxt * STG, Bb, K, (it + 1) << 6);
        }
        cp_commit();
        cp_wait1();
        __syncthreads();
        const uint32_t ca = sa + cur * STG, cb = sb + cur * STG;
        #pragma unroll
        for (int ks = 0; ks < 4; ++ks) {
            uint32_t a[2][4];
            ldm_x4(a[0][0], a[0][1], a[0][2], a[0][3], ca + aoff + ks * 32);
            ldm_x4(a[1][0], a[1][1], a[1][2], a[1][3], ca + aoff + 16 * HAST * 2 + ks * 32);
            #pragma unroll
            for (int nt2 = 0; nt2 < 4; ++nt2) {
                uint32_t b0e, b1e, b0o, b1o;
                ldm_x4(b0e, b1e, b0o, b1o, cb + boff + nt2 * (16 * HAST * 2) + ks * 32);
                mma_f16(acc[0][2 * nt2],     a[0][0], a[0][1], a[0][2], a[0][3], b0e, b1e);
                mma_f16(acc[1][2 * nt2],     a[1][0], a[1][1], a[1][2], a[1][3], b0e, b1e);
                mma_f16(acc[0][2 * nt2 + 1], a[0][0], a[0][1], a[0][2], a[0][3], b0o, b1o);
                mma_f16(acc[1][2 * nt2 + 1], a[1][0], a[1][1], a[1][2], a[1][3], b0o, b1o);
            }
        }
        __syncthreads();
    }
    #pragma unroll
    for (int mt = 0; mt < 2; ++mt)
        #pragma unroll
        for (int nt = 0; nt < 8; ++nt) {
            const int row = m0 + wm * 32 + mt * 16 + g;
            const int col = n0 + wn * 64 + nt * 8 + tig * 2;
            float2 bv = *(const float2*)(bias + col);
            float o0x = acc[mt][nt][0] + bv.x, o0y = acc[mt][nt][1] + bv.y;
            float o1x = acc[mt][nt][2] + bv.x, o1y = acc[mt][nt][3] + bv.y;
            if (RELU) {
                o0x = fmaxf(o0x, 0.f); o0y = fmaxf(o0y, 0.f);
                o1x = fmaxf(o1x, 0.f); o1y = fmaxf(o1y, 0.f);
            }
            if (HOUT) {
                __half* C = (__half*)Cv;
                *(__half2*)(C + (size_t)row * ldc + col) = __floats2half2_rn(o0x, o0y);
                *(__half2*)(C + (size_t)(row + 8) * ldc + col) = __floats2half2_rn(o1x, o1y);
            } else {
                float* C = (float*)Cv;
                *(float2*)(C + (size_t)row * ldc + col) = make_float2(o0x, o0y);
                *(float2*)(C + (size_t)(row + 8) * ldc + col) = make_float2(o1x, o1y);
            }
        }
}

// =================================================================
// Fused flash attention (fp16 mma, fp32 accum, online softmax).
// q,k read with row strides ldq/ldk (packed-QKV support).
// =================================================================
template<bool CAUSAL>
__global__ void __launch_bounds__(256, 2) flash_attn(
    const __half* __restrict__ qh, int ldq,
    const __half* __restrict__ kh, int ldk,
    const __half* __restrict__ vt, float* __restrict__ outm)
{
    const int z = blockIdx.y, b = z >> 4, h = z & 15;
    const int xt = CAUSAL ? ((int)gridDim.x - 1 - (int)blockIdx.x) : (int)blockIdx.x;
    const int m0 = xt << 7;
    extern __shared__ __half sh[];
    __half* sQ = sh;
    __half* sK = sh + 128 * QST;
    __half* sV = sh + 2 * 128 * QST;
    const int tid = threadIdx.x;
    const int wid = tid >> 5, lane = tid & 31;
    const int g = lane >> 2, tig = lane & 3;
    const uint32_t sq = smem_u32(sQ), sk = smem_u32(sK), sv = smem_u32(sV);

    // per-lane ldmatrix offsets (bytes)
    const uint32_t qoff = (uint32_t)(((wid * 16 + (lane & 15)) * QST + ((lane >> 4) << 3)) * 2);
    const uint32_t koff = (uint32_t)((((lane & 7) + ((lane >> 4) << 3)) * KST + (lane & 8)) * 2);
    const uint32_t voff = (uint32_t)((((lane & 7) + ((lane >> 4) << 3)) * VST + (lane & 8)) * 2);

    {
        const __half* src = qh + ((size_t)b * SEQ + m0) * ldq + h * HDK;
        #pragma unroll
        for (int j = 0; j < 4; ++j) {
            const int idx = tid + (j << 8);
            const int row = idx >> 3, c8 = (idx & 7) << 3;
            cp_async16(sq + (uint32_t)(row * QST + c8) * 2, src + (size_t)row * ldq + c8);
        }
    }

    float accO[8][4] = {};
    float mrow0 = -INFINITY, mrow1 = -INFINITY;
    float lrow0 = 0.f, lrow1 = 0.f;
    const int r0loc = wid * 16 + g;

    const int ntiles = CAUSAL ? (xt + 1) : (SEQ >> 7);
    for (int t = 0; t < ntiles; ++t) {
        const int n0 = t << 7;
        {
            const __half* ks = kh + ((size_t)b * SEQ + n0) * ldk + h * HDK;
            #pragma unroll
            for (int j = 0; j < 4; ++j) {
                const int idx = tid + (j << 8);
                const int row = idx >> 3, c8 = (idx & 7) << 3;
                cp_async16(sk + (uint32_t)(row * KST + c8) * 2, ks + (size_t)row * ldk + c8);
            }
            const __half* vs = vt + (size_t)z * HDK * SEQ + n0;
            #pragma unroll
            for (int j = 0; j < 4; ++j) {
                const int idx = tid + (j << 8);
                const int row = idx >> 4, c8 = (idx & 15) << 3;
                cp_async16(sv + (uint32_t)(row * VST + c8) * 2, vs + (size_t)row * SEQ + c8);
            }
        }
        cp_commit();
        cp_wait0();
        __syncthreads();

        // ---- S = Q.K^T ----
        float accS[16][4];
        #pragma unroll
        for (int nt = 0; nt < 16; ++nt) {
            accS[nt][0] = 0.f; accS[nt][1] = 0.f; accS[nt][2] = 0.f; accS[nt][3] = 0.f;
        }
        #pragma unroll
        for (int ks = 0; ks < 4; ++ks) {
            uint32_t a0, a1, a2, a3;
            ldm_x4(a0, a1, a2, a3, sq + qoff + ks * 32);
            #pragma unroll
            for (int nt2 = 0; nt2 < 8; ++nt2) {
                uint32_t b0e, b1e, b0o, b1o;
                ldm_x4(b0e, b1e, b0o, b1o, sk + koff + nt2 * (16 * KST * 2) + ks * 32);
                mma_f16(accS[2 * nt2],     a0, a1, a2, a3, b0e, b1e);
                mma_f16(accS[2 * nt2 + 1], a0, a1, a2, a3, b0o, b1o);
            }
        }

        // ---- scale + (diagonal) mask + row max ----
        float mn0 = mrow0, mn1 = mrow1;
        #pragma unroll
        for (int nt = 0; nt < 16; ++nt) {
            if (CAUSAL && n0 == m0) {
                const int col = nt * 8 + 2 * tig;
                if (col     > r0loc)     accS[nt][0] = -INFINITY;
                if (col + 1 > r0loc)     accS[nt][1] = -INFINITY;
                if (col     > r0loc + 8) accS[nt][2] = -INFINITY;
                if (col + 1 > r0loc + 8) accS[nt][3] = -INFINITY;
            }
            accS[nt][0] *= 0.125f; accS[nt][1] *= 0.125f;
            accS[nt][2] *= 0.125f; accS[nt][3] *= 0.125f;
            mn0 = fmaxf(mn0, fmaxf(accS[nt][0], accS[nt][1]));
            mn1 = fmaxf(mn1, fmaxf(accS[nt][2], accS[nt][3]));
        }
        mn0 = fmaxf(mn0, __shfl_xor_sync(0xFFFFFFFFu, mn0, 1));
        mn0 = fmaxf(mn0, __shfl_xor_sync(0xFFFFFFFFu, mn0, 2));
        mn1 = fmaxf(mn1, __shfl_xor_sync(0xFFFFFFFFu, mn1, 1));
        mn1 = fmaxf(mn1, __shfl_xor_sync(0xFFFFFFFFu, mn1, 2));
        const float cf0 = __expf(mrow0 - mn0);
        const float cf1 = __expf(mrow1 - mn1);
        mrow0 = mn0; mrow1 = mn1;
        #pragma unroll
        for (int nt = 0; nt < 8; ++nt) {
            accO[nt][0] *= cf0; accO[nt][1] *= cf0;
            accO[nt][2] *= cf1; accO[nt][3] *= cf1;
        }

        // ---- exp -> pack -> PV mma ----
        float rs0 = 0.f, rs1 = 0.f;
        #pragma unroll
        for (int k2 = 0; k2 < 8; ++k2) {
            const float e00 = __expf(accS[2 * k2][0] - mn0);
            const float e01 = __expf(accS[2 * k2][1] - mn0);
            const float e02 = __expf(accS[2 * k2][2] - mn1);
            const float e03 = __expf(accS[2 * k2][3] - mn1);
            const float e10 = __expf(accS[2 * k2 + 1][0] - mn0);
            const float e11 = __expf(accS[2 * k2 + 1][1] - mn0);
            const float e12 = __expf(accS[2 * k2 + 1][2] - mn1);
            const float e13 = __expf(accS[2 * k2 + 1][3] - mn1);
            rs0 += e00 + e01 + e10 + e11;
            rs1 += e02 + e03 + e12 + e13;
            const uint32_t pa0 = pack_h2(e00, e01);
            const uint32_t pa1 = pack_h2(e02, e03);
            const uint32_t pa2 = pack_h2(e10, e11);
            const uint32_t pa3 = pack_h2(e12, e13);
            #pragma unroll
            for (int nt2 = 0; nt2 < 4; ++nt2) {
                uint32_t b0e, b1e, b0o, b1o;
                ldm_x4(b0e, b1e, b0o, b1o, sv + voff + nt2 * (16 * VST * 2) + k2 * 32);
                mma_f16(accO[2 * nt2],     pa0, pa1, pa2, pa3, b0e, b1e);
                mma_f16(accO[2 * nt2 + 1], pa0, pa1, pa2, pa3, b0o, b1o);
            }
        }
        rs0 += __shfl_xor_sync(0xFFFFFFFFu, rs0, 1);
        rs0 += __shfl_xor_sync(0xFFFFFFFFu, rs0, 2);
        rs1 += __shfl_xor_sync(0xFFFFFFFFu, rs1, 1);
        rs1 += __shfl_xor_sync(0xFFFFFFFFu, rs1, 2);
        lrow0 = lrow0 * cf0 + rs0;
        lrow1 = lrow1 * cf1 + rs1;
        __syncthreads();
    }

    const float inv0 = 1.f / lrow0, inv1 = 1.f / lrow1;
    const int row = m0 + r0loc;
    float* o0 = outm + ((size_t)b * SEQ + row) * DIM + h * HDK;
    #pragma unroll
    for (int nt = 0; nt < 8; ++nt) {
        const int col = nt * 8 + 2 * tig;
        *(float2*)(o0 + col) = make_float2(accO[nt][0] * inv0, accO[nt][1] * inv0);
        *(float2*)(o0 + 8 * DIM + col) = make_float2(accO[nt][2] * inv1, accO[nt][3] * inv1);
    }
}

// =================================================================
// Fused seq-norm (quirk: normalize over S, divide by unbiased VARIANCE)
// =================================================================
template<bool HOUT>
__global__ void __launch_bounds__(256) seq_norm(
    const float* __restrict__ x, const float* __restrict__ res,
    float* __restrict__ out, __half* __restrict__ outh)
{
    const int d = blockIdx.x * 16 + threadIdx.x;
    const int b = blockIdx.y;
    const int ty = threadIdx.y;
    double s1 = 0.0, s2 = 0.0;
    for (int s = ty; s < SEQ; s += 16) {
        const size_t idx = ((size_t)b * SEQ + s) * DIM + d;
        const float vv = x[idx] + res[idx];
        s1 += vv;
        s2 += (double)vv * (double)vv;
    }
    __shared__ double sm1[16][16];
    __shared__ double sm2[16][16];
    __shared__ float smean[16], sivar[16];
    sm1[ty][threadIdx.x] = s1;
    sm2[ty][threadIdx.x] = s2;
    __syncthreads();
    if (ty == 0) {
        #pragma unroll
        for (int r = 1; r < 16; ++r) { s1 += sm1[r][threadIdx.x]; s2 += sm2[r][threadIdx.x]; }
        const double m   = s1 / (double)SEQ;
        const double var = (s2 - (double)SEQ * m * m) / (double)(SEQ - 1);
        smean[threadIdx.x] = (float)m;
        sivar[threadIdx.x] = (float)(1.0 / var);
    }
    __syncthreads();
    const float m = smean[threadIdx.x], ivr = sivar[threadIdx.x];
    for (int s = ty; s < SEQ; s += 16) {
        const size_t idx = ((size_t)b * SEQ + s) * DIM + d;
        const float o = (x[idx] + res[idx] - m) * ivr;
        out[idx] = o;
        if (HOUT) outh[idx] = __float2half(o);
    }
}

// =================================================================
// Host-side launcher
// =================================================================
extern "C" void kernel_launch(void* const* d_in, const int* in_sizes, int n_in,
                              void* d_out, int out_size)
{
    (void)in_sizes; (void)n_in; (void)out_size;
    const float* dec = (const float*)d_in[0];
    const float* enc = (const float*)d_in[1];
    const float* Wq1 = (const float*)d_in[2];
    const float* Wk1 = (const float*)d_in[3];
    const float* Wv1 = (const float*)d_in[4];
    const float* bq1 = (const float*)d_in[5];
    const float* bk1 = (const float*)d_in[6];
    const float* bv1 = (const float*)d_in[7];
    const float* Wq2 = (const float*)d_in[8];
    const float* Wk2 = (const float*)d_in[9];
    const float* Wv2 = (const float*)d_in[10];
    const float* bq2 = (const float*)d_in[11];
    const float* bk2 = (const float*)d_in[12];
    const float* bv2 = (const float*)d_in[13];
    const float* W1  = (const float*)d_in[14];
    const float* b1  = (const float*)d_in[15];
    const float* W2  = (const float*)d_in[16];
    const float* b2  = (const float*)d_in[17];
    float* out = (float*)d_out;

    float *t0, *x1, *x2, *bias3;
    __half *dech, *ench, *x1h, *x2h, *ffnh, *qkvh, *qh, *vtb, *wth, *w1t, *w2t;
    cudaGetSymbolAddress((void**)&t0,   g_t0);
    cudaGetSymbolAddress((void**)&x1,   g_x1);
    cudaGetSymbolAddress((void**)&x2,   g_x2);
    cudaGetSymbolAddress((void**)&dech, g_dech);
    cudaGetSymbolAddress((void**)&ench, g_ench);
    cudaGetSymbolAddress((void**)&x1h,  g_x1h);
    cudaGetSymbolAddress((void**)&x2h,  g_x2h);
    cudaGetSymbolAddress((void**)&ffnh, g_ffnh);
    cudaGetSymbolAddress((void**)&qkvh, g_qkvh);
    cudaGetSymbolAddress((void**)&qh,   g_qh);
    cudaGetSymbolAddress((void**)&vtb,  g_vt);
    cudaGetSymbolAddress((void**)&wth,  g_wth);
    cudaGetSymbolAddress((void**)&w1t,  g_w1t);
    cudaGetSymbolAddress((void**)&w2t,  g_w2t);
    cudaGetSymbolAddress((void**)&bias3, g_bias3);
    __half* wq1t = wth + 0 * (size_t)DIM * DIM;
    __half* wk1t = wth + 1 * (size_t)DIM * DIM;
    __half* wv1t = wth + 2 * (size_t)DIM * DIM;
    __half* wq2t = wth + 3 * (size_t)DIM * DIM;
    __half* wk2t = wth + 4 * (size_t)DIM * DIM;
    __half* wv2t = wth + 5 * (size_t)DIM * DIM;

    cudaFuncSetAttribute(hgemm<false, false>, cudaFuncAttributeMaxDynamicSharedMemorySize, HG_SMEM);
    cudaFuncSetAttribute(hgemm<false, true>,  cudaFuncAttributeMaxDynamicSharedMemorySize, HG_SMEM);
    cudaFuncSetAttribute(hgemm<true,  true>,  cudaFuncAttributeMaxDynamicSharedMemorySize, HG_SMEM);
    cudaFuncSetAttribute(flash_attn<true>,  cudaFuncAttributeMaxDynamicSharedMemorySize, FA_SMEM);
    cudaFuncSetAttribute(flash_attn<false>, cudaFuncAttributeMaxDynamicSharedMemorySize, FA_SMEM);

    const dim3 bT(32, 8);
    const dim3 gWsq(DIM / 32, DIM / 32);
    const dim3 gW1 (FFD / 32, DIM / 32);
    const dim3 gW2 (DIM / 32, FFD / 32);
    const dim3 gQKV(3 * DIM / 128, MROWS / 128);         // (24, 32)
    const dim3 gKV (2 * DIM / 128, MROWS / 128);         // (16, 32)
    const dim3 gProj(DIM / 128, MROWS / 128);            // (8, 32)
    const dim3 gFf1 (FFD / 128, MROWS / 128);            // (32, 32)
    const dim3 gTv  (HDK / 32, SEQ / 32, BH);
    const dim3 gFA  (SEQ / 128, BH);
    const dim3 gNorm(DIM / 16, BATCH);
    const dim3 bNorm(16, 16);
    const int  nCvt = (int)(((size_t)MROWS * DIM) / 1024);

    // ---------- weight + input conversion ----------
    cvt_w_t<<<gWsq, bT>>>(Wq1, wq1t, DIM, DIM);
    cvt_w_t<<<gWsq, bT>>>(Wk1, wk1t, DIM, DIM);
    cvt_w_t<<<gWsq, bT>>>(Wv1, wv1t, DIM, DIM);
    cvt_w_t<<<gWsq, bT>>>(Wq2, wq2t, DIM, DIM);
    cvt_w_t<<<gWsq, bT>>>(Wk2, wk2t, DIM, DIM);
    cvt_w_t<<<gWsq, bT>>>(Wv2, wv2t, DIM, DIM);
    cvt_w_t<<<gW1,  bT>>>(W1,  w1t,  DIM, FFD);
    cvt_w_t<<<gW2,  bT>>>(W2,  w2t,  FFD, DIM);
    cvt_act<<<nCvt, 256>>>(dec, dech);
    cvt_act<<<nCvt, 256>>>(enc, ench);

    // ---------- sublayer 1: causal self-attention (fused QKV) ----------
    concat_bias3<<<12, 256>>>(bq1, bk1, bv1, bias3, 3);
    hgemm<false, true><<<gQKV, 256, HG_SMEM>>>(dech, wq1t, bias3, qkvh, DIM, 3 * DIM);
    transpose_vh<<<gTv, bT>>>(qkvh + 2 * DIM, 3 * DIM, vtb);
    flash_attn<true><<<gFA, 256, FA_SMEM>>>(qkvh, 3 * DIM, qkvh + DIM, 3 * DIM, vtb, t0);
    seq_norm<true><<<gNorm, bNorm>>>(t0, dec, x1, x1h);

    // ---------- sublayer 2: cross-attention (fused KV) ----------
    concat_bias3<<<12, 256>>>(bk2, bv2, bv2, bias3, 2);
    hgemm<false, true><<<gProj, 256, HG_SMEM>>>(x1h, wq2t, bq2, qh, DIM, DIM);
    hgemm<false, true><<<gKV,   256, HG_SMEM>>>(ench, wk2t, bias3, qkvh, DIM, 2 * DIM);
    transpose_vh<<<gTv, bT>>>(qkvh + DIM, 2 * DIM, vtb);
    flash_attn<false><<<gFA, 256, FA_SMEM>>>(qh, DIM, qkvh, 2 * DIM, vtb, t0);
    seq_norm<true><<<gNorm, bNorm>>>(t0, x1, x2, x2h);

    // ---------- sublayer 3: FFN ----------
    hgemm<true,  true ><<<gFf1,  256, HG_SMEM>>>(x2h,  w1t, b1, ffnh, DIM, FFD);
    hgemm<false, false><<<gProj, 256, HG_SMEM>>>(ffnh, w2t, b2, t0,   FFD, DIM);
    seq_norm<false><<<gNorm, bNorm>>>(t0, x2, out, nullptr);
}

// round 9
// speedup vs baseline: 7.0126x; 1.0767x over previous
#include <cuda_runtime.h>
#include <cuda_fp16.h>
#include <cstdint>
#include <math.h>

// ---------------- problem constants ----------------
#define BATCH  2
#define SEQ    2048
#define DIM    1024
#define HEADS  16
#define HDK    64
#define FFD    4096
#define MROWS  (BATCH * SEQ)          // 4096
#define BH     (BATCH * HEADS)        // 32

// hgemm smem: A k-major [128][72], B n-major [64][136]
#define HAST 72
#define BNST 136
#define A_STG (128 * HAST)            // halves per A stage
#define B_STG (64 * BNST)             // halves per B stage
#define HG_SMEM ((2 * A_STG + 2 * B_STG) * 2)   // 71680 bytes

// flash smem: Q [128][72]; 2 stages x (K [128][72] + V [128][72])
#define KVST 72
#define FA_STAGE_B (2 * 128 * KVST * 2)          // 36864 bytes per stage
#define FA_SMEM ((128 * KVST) * 2 + 2 * FA_STAGE_B)  // 92160 bytes

// ---------------- device scratch ----------------
__device__ float  g_t0 [(size_t)MROWS * DIM];
__device__ float  g_x1 [(size_t)MROWS * DIM];
__device__ float  g_x2 [(size_t)MROWS * DIM];
__device__ __half g_dech[(size_t)MROWS * DIM];
__device__ __half g_ench[(size_t)MROWS * DIM];
__device__ __half g_x1h [(size_t)MROWS * DIM];
__device__ __half g_x2h [(size_t)MROWS * DIM];
__device__ __half g_ffnh[(size_t)MROWS * FFD];
__device__ __half g_qkvh[(size_t)MROWS * 3 * DIM];  // fused QKV / KV outputs
__device__ __half g_qh  [(size_t)MROWS * DIM];      // sublayer2 Q
__device__ __half g_wqkv1h[(size_t)DIM * 3 * DIM];  // packed [K, 3N] n-major
__device__ __half g_wq2h  [(size_t)DIM * DIM];
__device__ __half g_wkv2h [(size_t)DIM * 2 * DIM];
__device__ __half g_w1h   [(size_t)DIM * FFD];
__device__ __half g_w2h   [(size_t)FFD * DIM];
__device__ float  g_bias3[3 * DIM];

// ---------------- PTX helpers (sm_100 base target) ----------------
__device__ __forceinline__ uint32_t smem_u32(const void* p) {
    uint32_t a;
    asm("{ .reg .u64 t; cvta.to.shared.u64 t, %1; cvt.u32.u64 %0, t; }" : "=r"(a) : "l"(p));
    return a;
}
__device__ __forceinline__ void cp_async16(uint32_t saddr, const void* g) {
    asm volatile("cp.async.cg.shared.global [%0], [%1], 16;" :: "r"(saddr), "l"(g) : "memory");
}
__device__ __forceinline__ void cp_commit() {
    asm volatile("cp.async.commit_group;" ::: "memory");
}
__device__ __forceinline__ void cp_wait1() {
    asm volatile("cp.async.wait_group 1;" ::: "memory");
}
__device__ __forceinline__ void cp_wait0() {
    asm volatile("cp.async.wait_group 0;" ::: "memory");
}
__device__ __forceinline__ void mma_f16(float c[4],
    uint32_t a0, uint32_t a1, uint32_t a2, uint32_t a3, uint32_t b0, uint32_t b1) {
    asm volatile(
        "mma.sync.aligned.m16n8k16.row.col.f32.f16.f16.f32 "
        "{%0,%1,%2,%3}, {%4,%5,%6,%7}, {%8,%9}, {%0,%1,%2,%3};"
        : "+f"(c[0]), "+f"(c[1]), "+f"(c[2]), "+f"(c[3])
        : "r"(a0), "r"(a1), "r"(a2), "r"(a3), "r"(b0), "r"(b1));
}
__device__ __forceinline__ void ldm_x4(uint32_t& r0, uint32_t& r1, uint32_t& r2, uint32_t& r3,
                                       uint32_t addr) {
    asm volatile("ldmatrix.sync.aligned.m8n8.x4.shared.b16 {%0,%1,%2,%3}, [%4];"
                 : "=r"(r0), "=r"(r1), "=r"(r2), "=r"(r3) : "r"(addr));
}
__device__ __forceinline__ void ldm_x4_t(uint32_t& r0, uint32_t& r1, uint32_t& r2, uint32_t& r3,
                                         uint32_t addr) {
    asm volatile("ldmatrix.sync.aligned.m8n8.x4.trans.shared.b16 {%0,%1,%2,%3}, [%4];"
                 : "=r"(r0), "=r"(r1), "=r"(r2), "=r"(r3) : "r"(addr));
}
__device__ __forceinline__ uint32_t pack_h2(float x, float y) {
    __half2 h = __floats2half2_rn(x, y);
    return *(uint32_t*)&h;
}

// =================================================================
// Converters (flat f32 -> f16; layouts preserved)
// =================================================================
__global__ void __launch_bounds__(256) cvt_flat(const float* __restrict__ in,
                                                __half* __restrict__ out)
{
    const size_t i = ((size_t)blockIdx.x * 256 + threadIdx.x) * 4;
    float4 v = *(const float4*)(in + i);
    *(__half2*)(out + i) = __floats2half2_rn(v.x, v.y);
    *(__half2*)(out + i + 2) = __floats2half2_rn(v.z, v.w);
}

// pack 6 projection weights [DIM,DIM] f32 into fused f16 buffers:
// z=0..2 -> wqkv1 (stride 3*DIM, col off z*DIM); z=3 -> wq2; z=4..5 -> wkv2
__global__ void __launch_bounds__(256) cvt_pack6(
    const float* __restrict__ p0, const float* __restrict__ p1,
    const float* __restrict__ p2, const float* __restrict__ p3,
    const float* __restrict__ p4, const float* __restrict__ p5,
    __half* __restrict__ qkv1, __half* __restrict__ q2, __half* __restrict__ kv2)
{
    const int z = blockIdx.y;
    const size_t i = ((size_t)blockIdx.x * 256 + threadIdx.x) * 4;
    const int k = (int)(i >> 10), n = (int)(i & (DIM - 1));
    const float* src = (z == 0) ? p0 : (z == 1) ? p1 : (z == 2) ? p2
                     : (z == 3) ? p3 : (z == 4) ? p4 : p5;
    float4 v = *(const float4*)(src + i);
    __half* dst;
    int stride, off;
    if (z < 3)      { dst = qkv1; stride = 3 * DIM; off = z * DIM; }
    else if (z == 3){ dst = q2;   stride = DIM;     off = 0; }
    else            { dst = kv2;  stride = 2 * DIM; off = (z - 4) * DIM; }
    __half* d = dst + (size_t)k * stride + off + n;
    *(__half2*)(d)     = __floats2half2_rn(v.x, v.y);
    *(__half2*)(d + 2) = __floats2half2_rn(v.z, v.w);
}

__global__ void __launch_bounds__(256) concat_bias3(
    const float* __restrict__ b0, const float* __restrict__ b1,
    const float* __restrict__ b2, float* __restrict__ out, int n)
{
    const int i = blockIdx.x * 256 + threadIdx.x;
    if (i >= n * DIM) return;
    const int seg = i >> 10, off = i & (DIM - 1);
    const float* src = (seg == 0) ? b0 : (seg == 1) ? b1 : b2;
    out[i] = src[off];
}

// =================================================================
// fp16 HGEMM: C[M,N] = A[M,K] @ W[K,N] + bias. 128x128x64 tiles.
// A k-major, W n-major (ldmatrix.trans B fragments).
// =================================================================
__device__ __forceinline__ void hload_A(uint32_t sbase, const __half* G, int ldg, int k0) {
    const int t = threadIdx.x;
    #pragma unroll
    for (int j = 0; j < 4; ++j) {                 // 128 rows x 64 halves
        const int idx = t + (j << 8);
        const int row = idx >> 3, c8 = (idx & 7) << 3;
        cp_async16(sbase + (uint32_t)(row * HAST + c8) * 2, G + (size_t)row * ldg + k0 + c8);
    }
}
__device__ __forceinline__ void hload_B(uint32_t sbase, const __half* G, int ldg, int k0) {
    const int t = threadIdx.x;
    #pragma unroll
    for (int j = 0; j < 4; ++j) {                 // 64 rows x 128 halves
        const int idx = t + (j << 8);
        const int row = idx >> 4, c8 = (idx & 15) << 3;
        cp_async16(sbase + (uint32_t)(row * BNST + c8) * 2, G + (size_t)(k0 + row) * ldg + c8);
    }
}

template<bool RELU, bool HOUT>
__global__ void __launch_bounds__(256) hgemm(
    const __half* __restrict__ A, const __half* __restrict__ W,
    const float* __restrict__ bias, void* __restrict__ Cv, int K, int ldb, int ldc)
{
    extern __shared__ __half sh[];
    const int m0 = blockIdx.y << 7, n0 = blockIdx.x << 7;
    const uint32_t sa = smem_u32(sh);
    const uint32_t sb = sa + 2 * A_STG * 2;
    const __half* Ab = A + (size_t)m0 * K;
    const __half* Bb = W + n0;
    const int kiters = K >> 6;
    const int lane = threadIdx.x & 31, warp = threadIdx.x >> 5;
    const int wm = warp >> 1, wn = warp & 1;
    const int g = lane >> 2, tig = lane & 3;

    // ldmatrix lane offsets (bytes)
    const uint32_t aoff = (uint32_t)(((wm * 32 + (lane & 15)) * HAST + ((lane >> 4) << 3)) * 2);
    // trans B: rows k = (lane&7) + 8*bit3, cols n = wn*64 + 8*bit4
    const uint32_t boff = (uint32_t)((((lane & 7) + (((lane >> 3) & 1) << 3)) * BNST
                                      + wn * 64 + ((lane >> 4) << 3)) * 2);

    float acc[2][8][4] = {};
    hload_A(sa, Ab, K, 0);
    hload_B(sb, Bb, ldb, 0);
    cp_commit();
    for (int it = 0; it < kiters; ++it) {
        const int cur = it & 1, nxt = cur ^ 1;
        if (it + 1 < kiters) {
            hload_A(sa + nxt * A_STG * 2, Ab, K, (it + 1) << 6);
            hload_B(sb + nxt * B_STG * 2, Bb, ldb, (it + 1) << 6);
            cp_commit();
            cp_wait1();
        } else {
            cp_wait0();
        }
        __syncthreads();
        const uint32_t ca = sa + cur * A_STG * 2, cb = sb + cur * B_STG * 2;
        #pragma unroll
        for (int ks = 0; ks < 4; ++ks) {
            uint32_t a[2][4];
            ldm_x4(a[0][0], a[0][1], a[0][2], a[0][3], ca + aoff + ks * 32);
            ldm_x4(a[1][0], a[1][1], a[1][2], a[1][3], ca + aoff + 16 * HAST * 2 + ks * 32);
            #pragma unroll
            for (int nt2 = 0; nt2 < 4; ++nt2) {
                uint32_t b0e, b1e, b0o, b1o;
                ldm_x4_t(b0e, b1e, b0o, b1o,
                         cb + boff + (uint32_t)((ks * 16 * BNST + nt2 * 16) * 2));
                mma_f16(acc[0][2 * nt2],     a[0][0], a[0][1], a[0][2], a[0][3], b0e, b1e);
                mma_f16(acc[1][2 * nt2],     a[1][0], a[1][1], a[1][2], a[1][3], b0e, b1e);
                mma_f16(acc[0][2 * nt2 + 1], a[0][0], a[0][1], a[0][2], a[0][3], b0o, b1o);
                mma_f16(acc[1][2 * nt2 + 1], a[1][0], a[1][1], a[1][2], a[1][3], b0o, b1o);
            }
        }
        __syncthreads();
    }
    #pragma unroll
    for (int mt = 0; mt < 2; ++mt)
        #pragma unroll
        for (int nt = 0; nt < 8; ++nt) {
            const int row = m0 + wm * 32 + mt * 16 + g;
            const int col = n0 + wn * 64 + nt * 8 + tig * 2;
            float2 bv = *(const float2*)(bias + col);
            float o0x = acc[mt][nt][0] + bv.x, o0y = acc[mt][nt][1] + bv.y;
            float o1x = acc[mt][nt][2] + bv.x, o1y = acc[mt][nt][3] + bv.y;
            if (RELU) {
                o0x = fmaxf(o0x, 0.f); o0y = fmaxf(o0y, 0.f);
                o1x = fmaxf(o1x, 0.f); o1y = fmaxf(o1y, 0.f);
            }
            if (HOUT) {
                __half* C = (__half*)Cv;
                *(__half2*)(C + (size_t)row * ldc + col) = __floats2half2_rn(o0x, o0y);
                *(__half2*)(C + (size_t)(row + 8) * ldc + col) = __floats2half2_rn(o1x, o1y);
            } else {
                float* C = (float*)Cv;
                *(float2*)(C + (size_t)row * ldc + col) = make_float2(o0x, o0y);
                *(float2*)(C + (size_t)(row + 8) * ldc + col) = make_float2(o1x, o1y);
            }
        }
}

// =================================================================
// Fused flash attention. V read un-transposed via ldmatrix.trans.
// Double-buffered K/V tiles.
// =================================================================
template<bool CAUSAL>
__global__ void __launch_bounds__(256, 2) flash_attn(
    const __half* __restrict__ qh, int ldq,
    const __half* __restrict__ kh, int ldk,
    const __half* __restrict__ vh, int ldv,
    float* __restrict__ outm)
{
    const int z = blockIdx.y, b = z >> 4, h = z & 15;
    const int xt = CAUSAL ? ((int)gridDim.x - 1 - (int)blockIdx.x) : (int)blockIdx.x;
    const int m0 = xt << 7;
    extern __shared__ __half sh[];
    const int tid = threadIdx.x;
    const int wid = tid >> 5, lane = tid & 31;
    const int g = lane >> 2, tig = lane & 3;
    const uint32_t sq = smem_u32(sh);
    const uint32_t skv0 = sq + 128 * KVST * 2;

    const uint32_t qoff = (uint32_t)(((wid * 16 + (lane & 15)) * KVST + ((lane >> 4) << 3)) * 2);
    const uint32_t koff = (uint32_t)((((lane & 7) + ((lane >> 4) << 3)) * KVST + (lane & 8)) * 2);
    // trans V: rows s = (lane&7) + 8*bit3, cols dk = 8*bit4
    const uint32_t voff = (uint32_t)((((lane & 7) + (((lane >> 3) & 1) << 3)) * KVST
                                      + ((lane >> 4) << 3)) * 2);

    // Q tile
    {
        const __half* src = qh + ((size_t)b * SEQ + m0) * ldq + h * HDK;
        #pragma unroll
        for (int j = 0; j < 4; ++j) {
            const int idx = tid + (j << 8);
            const int row = idx >> 3, c8 = (idx & 7) << 3;
            cp_async16(sq + (uint32_t)(row * KVST + c8) * 2, src + (size_t)row * ldq + c8);
        }
    }

    auto load_kv = [&](int st, int n0) {
        const uint32_t base = skv0 + (uint32_t)st * FA_STAGE_B;
        const __half* ks = kh + ((size_t)b * SEQ + n0) * ldk + h * HDK;
        const __half* vs = vh + ((size_t)b * SEQ + n0) * ldv + h * HDK;
        const uint32_t vbase = base + 128 * KVST * 2;
        #pragma unroll
        for (int j = 0; j < 4; ++j) {
            const int idx = tid + (j << 8);
            const int row = idx >> 3, c8 = (idx & 7) << 3;
            cp_async16(base  + (uint32_t)(row * KVST + c8) * 2, ks + (size_t)row * ldk + c8);
            cp_async16(vbase + (uint32_t)(row * KVST + c8) * 2, vs + (size_t)row * ldv + c8);
        }
    };

    float accO[8][4] = {};
    float mrow0 = -INFINITY, mrow1 = -INFINITY;
    float lrow0 = 0.f, lrow1 = 0.f;
    const int r0loc = wid * 16 + g;

    const int ntiles = CAUSAL ? (xt + 1) : (SEQ >> 7);
    load_kv(0, 0);
    cp_commit();
    for (int t = 0; t < ntiles; ++t) {
        const int n0 = t << 7;
        if (t + 1 < ntiles) {
            load_kv((t + 1) & 1, (t + 1) << 7);
            cp_commit();
            cp_wait1();
        } else {
            cp_wait0();
        }
        __syncthreads();
        const uint32_t skt = skv0 + (uint32_t)(t & 1) * FA_STAGE_B;
        const uint32_t svt = skt + 128 * KVST * 2;

        // ---- S = Q.K^T ----
        float accS[16][4];
        #pragma unroll
        for (int nt = 0; nt < 16; ++nt) {
            accS[nt][0] = 0.f; accS[nt][1] = 0.f; accS[nt][2] = 0.f; accS[nt][3] = 0.f;
        }
        #pragma unroll
        for (int ks = 0; ks < 4; ++ks) {
            uint32_t a0, a1, a2, a3;
            ldm_x4(a0, a1, a2, a3, sq + qoff + ks * 32);
            #pragma unroll
            for (int nt2 = 0; nt2 < 8; ++nt2) {
                uint32_t b0e, b1e, b0o, b1o;
                ldm_x4(b0e, b1e, b0o, b1o, skt + koff + nt2 * (16 * KVST * 2) + ks * 32);
                mma_f16(accS[2 * nt2],     a0, a1, a2, a3, b0e, b1e);
                mma_f16(accS[2 * nt2 + 1], a0, a1, a2, a3, b0o, b1o);
            }
        }

        // ---- scale + diagonal mask + row max ----
        float mn0 = mrow0, mn1 = mrow1;
        #pragma unroll
        for (int nt = 0; nt < 16; ++nt) {
            if (CAUSAL && n0 == m0) {
                const int col = nt * 8 + 2 * tig;
                if (col     > r0loc)     accS[nt][0] = -INFINITY;
                if (col + 1 > r0loc)     accS[nt][1] = -INFINITY;
                if (col     > r0loc + 8) accS[nt][2] = -INFINITY;
                if (col + 1 > r0loc + 8) accS[nt][3] = -INFINITY;
            }
            accS[nt][0] *= 0.125f; accS[nt][1] *= 0.125f;
            accS[nt][2] *= 0.125f; accS[nt][3] *= 0.125f;
            mn0 = fmaxf(mn0, fmaxf(accS[nt][0], accS[nt][1]));
            mn1 = fmaxf(mn1, fmaxf(accS[nt][2], accS[nt][3]));
        }
        mn0 = fmaxf(mn0, __shfl_xor_sync(0xFFFFFFFFu, mn0, 1));
        mn0 = fmaxf(mn0, __shfl_xor_sync(0xFFFFFFFFu, mn0, 2));
        mn1 = fmaxf(mn1, __shfl_xor_sync(0xFFFFFFFFu, mn1, 1));
        mn1 = fmaxf(mn1, __shfl_xor_sync(0xFFFFFFFFu, mn1, 2));
        const float cf0 = __expf(mrow0 - mn0);
        const float cf1 = __expf(mrow1 - mn1);
        mrow0 = mn0; mrow1 = mn1;
        #pragma unroll
        for (int nt = 0; nt < 8; ++nt) {
            accO[nt][0] *= cf0; accO[nt][1] *= cf0;
            accO[nt][2] *= cf1; accO[nt][3] *= cf1;
        }

        // ---- exp -> pack -> PV mma (V via ldmatrix.trans from [s][dk]) ----
        float rs0 = 0.f, rs1 = 0.f;
        #pragma unroll
        for (int k2 = 0; k2 < 8; ++k2) {
            const float e00 = __expf(accS[2 * k2][0] - mn0);
            const float e01 = __expf(accS[2 * k2][1] - mn0);
            const float e02 = __expf(accS[2 * k2][2] - mn1);
            const float e03 = __expf(accS[2 * k2][3] - mn1);
            const float e10 = __expf(accS[2 * k2 + 1][0] - mn0);
            const float e11 = __expf(accS[2 * k2 + 1][1] - mn0);
            const float e12 = __expf(accS[2 * k2 + 1][2] - mn1);
            const float e13 = __expf(accS[2 * k2 + 1][3] - mn1);
            rs0 += e00 + e01 + e10 + e11;
            rs1 += e02 + e03 + e12 + e13;
            const uint32_t pa0 = pack_h2(e00, e01);
            const uint32_t pa1 = pack_h2(e02, e03);
            const uint32_t pa2 = pack_h2(e10, e11);
            const uint32_t pa3 = pack_h2(e12, e13);
            #pragma unroll
            for (int nt2 = 0; nt2 < 4; ++nt2) {
                uint32_t b0e, b1e, b0o, b1o;
                ldm_x4_t(b0e, b1e, b0o, b1o,
                         svt + voff + (uint32_t)((k2 * 16 * KVST + nt2 * 16) * 2));
                mma_f16(accO[2 * nt2],     pa0, pa1, pa2, pa3, b0e, b1e);
                mma_f16(accO[2 * nt2 + 1], pa0, pa1, pa2, pa3, b0o, b1o);
            }
        }
        rs0 += __shfl_xor_sync(0xFFFFFFFFu, rs0, 1);
        rs0 += __shfl_xor_sync(0xFFFFFFFFu, rs0, 2);
        rs1 += __shfl_xor_sync(0xFFFFFFFFu, rs1, 1);
        rs1 += __shfl_xor_sync(0xFFFFFFFFu, rs1, 2);
        lrow0 = lrow0 * cf0 + rs0;
        lrow1 = lrow1 * cf1 + rs1;
        __syncthreads();
    }

    const float inv0 = 1.f / lrow0, inv1 = 1.f / lrow1;
    const int row = m0 + r0loc;
    float* o0 = outm + ((size_t)b * SEQ + row) * DIM + h * HDK;
    #pragma unroll
    for (int nt = 0; nt < 8; ++nt) {
        const int col = nt * 8 + 2 * tig;
        *(float2*)(o0 + col) = make_float2(accO[nt][0] * inv0, accO[nt][1] * inv0);
        *(float2*)(o0 + 8 * DIM + col) = make_float2(accO[nt][2] * inv1, accO[nt][3] * inv1);
    }
}

// =================================================================
// Fused seq-norm (quirk: normalize over S, divide by unbiased VARIANCE)
// =================================================================
template<bool HOUT>
__global__ void __launch_bounds__(256) seq_norm(
    const float* __restrict__ x, const float* __restrict__ res,
    float* __restrict__ out, __half* __restrict__ outh)
{
    const int d = blockIdx.x * 16 + threadIdx.x;
    const int b = blockIdx.y;
    const int ty = threadIdx.y;
    double s1 = 0.0, s2 = 0.0;
    for (int s = ty; s < SEQ; s += 16) {
        const size_t idx = ((size_t)b * SEQ + s) * DIM + d;
        const float vv = x[idx] + res[idx];
        s1 += vv;
        s2 += (double)vv * (double)vv;
    }
    __shared__ double sm1[16][16];
    __shared__ double sm2[16][16];
    __shared__ float smean[16], sivar[16];
    sm1[ty][threadIdx.x] = s1;
    sm2[ty][threadIdx.x] = s2;
    __syncthreads();
    if (ty == 0) {
        #pragma unroll
        for (int r = 1; r < 16; ++r) { s1 += sm1[r][threadIdx.x]; s2 += sm2[r][threadIdx.x]; }
        const double m   = s1 / (double)SEQ;
        const double var = (s2 - (double)SEQ * m * m) / (double)(SEQ - 1);
        smean[threadIdx.x] = (float)m;
        sivar[threadIdx.x] = (float)(1.0 / var);
    }
    __syncthreads();
    const float m = smean[threadIdx.x], ivr = sivar[threadIdx.x];
    for (int s = ty; s < SEQ; s += 16) {
        const size_t idx = ((size_t)b * SEQ + s) * DIM + d;
        const float o = (x[idx] + res[idx] - m) * ivr;
        out[idx] = o;
        if (HOUT) outh[idx] = __float2half(o);
    }
}

// =================================================================
// Host-side launcher
// =================================================================
extern "C" void kernel_launch(void* const* d_in, const int* in_sizes, int n_in,
                              void* d_out, int out_size)
{
    (void)in_sizes; (void)n_in; (void)out_size;
    const float* dec = (const float*)d_in[0];
    const float* enc = (const float*)d_in[1];
    const float* Wq1 = (const float*)d_in[2];
    const float* Wk1 = (const float*)d_in[3];
    const float* Wv1 = (const float*)d_in[4];
    const float* bq1 = (const float*)d_in[5];
    const float* bk1 = (const float*)d_in[6];
    const float* bv1 = (const float*)d_in[7];
    const float* Wq2 = (const float*)d_in[8];
    const float* Wk2 = (const float*)d_in[9];
    const float* Wv2 = (const float*)d_in[10];
    const float* bq2 = (const float*)d_in[11];
    const float* bk2 = (const float*)d_in[12];
    const float* bv2 = (const float*)d_in[13];
    const float* W1  = (const float*)d_in[14];
    const float* b1  = (const float*)d_in[15];
    const float* W2  = (const float*)d_in[16];
    const float* b2  = (const float*)d_in[17];
    float* out = (float*)d_out;

    float *t0, *x1, *x2, *bias3;
    __half *dech, *ench, *x1h, *x2h, *ffnh, *qkvh, *qh;
    __half *wqkv1h, *wq2h, *wkv2h, *w1h, *w2h;
    cudaGetSymbolAddress((void**)&t0,   g_t0);
    cudaGetSymbolAddress((void**)&x1,   g_x1);
    cudaGetSymbolAddress((void**)&x2,   g_x2);
    cudaGetSymbolAddress((void**)&dech, g_dech);
    cudaGetSymbolAddress((void**)&ench, g_ench);
    cudaGetSymbolAddress((void**)&x1h,  g_x1h);
    cudaGetSymbolAddress((void**)&x2h,  g_x2h);
    cudaGetSymbolAddress((void**)&ffnh, g_ffnh);
    cudaGetSymbolAddress((void**)&qkvh, g_qkvh);
    cudaGetSymbolAddress((void**)&qh,   g_qh);
    cudaGetSymbolAddress((void**)&wqkv1h, g_wqkv1h);
    cudaGetSymbolAddress((void**)&wq2h,   g_wq2h);
    cudaGetSymbolAddress((void**)&wkv2h,  g_wkv2h);
    cudaGetSymbolAddress((void**)&w1h,    g_w1h);
    cudaGetSymbolAddress((void**)&w2h,    g_w2h);
    cudaGetSymbolAddress((void**)&bias3,  g_bias3);

    cudaFuncSetAttribute(hgemm<false, false>, cudaFuncAttributeMaxDynamicSharedMemorySize, HG_SMEM);
    cudaFuncSetAttribute(hgemm<false, true>,  cudaFuncAttributeMaxDynamicSharedMemorySize, HG_SMEM);
    cudaFuncSetAttribute(hgemm<true,  true>,  cudaFuncAttributeMaxDynamicSharedMemorySize, HG_SMEM);
    cudaFuncSetAttribute(flash_attn<true>,  cudaFuncAttributeMaxDynamicSharedMemorySize, FA_SMEM);
    cudaFuncSetAttribute(flash_attn<false>, cudaFuncAttributeMaxDynamicSharedMemorySize, FA_SMEM);

    const dim3 gQKV(3 * DIM / 128, MROWS / 128);         // (24, 32)
    const dim3 gKV (2 * DIM / 128, MROWS / 128);         // (16, 32)
    const dim3 gProj(DIM / 128, MROWS / 128);            // (8, 32)
    const dim3 gFf1 (FFD / 128, MROWS / 128);            // (32, 32)
    const dim3 gFA  (SEQ / 128, BH);                     // (16, 32)
    const dim3 gNorm(DIM / 16, BATCH);
    const dim3 bNorm(16, 16);
    const dim3 gPack6(DIM * DIM / 1024, 6);
    const int  nCvtAct = (int)(((size_t)MROWS * DIM) / 1024);
    const int  nCvtW1  = (int)(((size_t)DIM * FFD) / 1024);

    // ---------- weight + input conversion ----------
    cvt_pack6<<<gPack6, 256>>>(Wq1, Wk1, Wv1, Wq2, Wk2, Wv2, wqkv1h, wq2h, wkv2h);
    cvt_flat<<<nCvtW1, 256>>>(W1, w1h);
    cvt_flat<<<nCvtW1, 256>>>(W2, w2h);
    cvt_flat<<<nCvtAct, 256>>>(dec, dech);
    cvt_flat<<<nCvtAct, 256>>>(enc, ench);

    // ---------- sublayer 1: causal self-attention (fused QKV) ----------
    concat_bias3<<<12, 256>>>(bq1, bk1, bv1, bias3, 3);
    hgemm<false, true><<<gQKV, 256, HG_SMEM>>>(dech, wqkv1h, bias3, qkvh, DIM, 3 * DIM, 3 * DIM);
    flash_attn<true><<<gFA, 256, FA_SMEM>>>(qkvh, 3 * DIM, qkvh + DIM, 3 * DIM,
                                            qkvh + 2 * DIM, 3 * DIM, t0);
    seq_norm<true><<<gNorm, bNorm>>>(t0, dec, x1, x1h);

    // ---------- sublayer 2: cross-attention (fused KV) ----------
    concat_bias3<<<12, 256>>>(bk2, bv2, bv2, bias3, 2);
    hgemm<false, true><<<gProj, 256, HG_SMEM>>>(x1h, wq2h, bq2, qh, DIM, DIM, DIM);
    hgemm<false, true><<<gKV,   256, HG_SMEM>>>(ench, wkv2h, bias3, qkvh, DIM, 2 * DIM, 2 * DIM);
    flash_attn<false><<<gFA, 256, FA_SMEM>>>(qh, DIM, qkvh, 2 * DIM,
                                             qkvh + DIM, 2 * DIM, t0);
    seq_norm<true><<<gNorm, bNorm>>>(t0, x1, x2, x2h);

    // ---------- sublayer 3: FFN ----------
    hgemm<true,  true ><<<gFf1,  256, HG_SMEM>>>(x2h,  w1h, b1, ffnh, DIM, FFD, FFD);
    hgemm<false, false><<<gProj, 256, HG_SMEM>>>(ffnh, w2h, b2, t0,   FFD, DIM, DIM);
    seq_norm<false><<<gNorm, bNorm>>>(t0, x2, out, nullptr);
}